// round 1
// baseline (speedup 1.0000x reference)
#include <cuda_runtime.h>
#include <cuda_bf16.h>
#include <cstdint>

// Problem constants (shapes from reference setup_inputs)
#define MAXN 50000
#define MAXE 600000
#define RNUM 16
#define DIN  64
#define HID  128

// ---------------- scratch (__device__ globals; no allocs allowed) -----------
__device__ float g_x1acc[(size_t)MAXN * HID];   // layer-1 accumulator
__device__ float g_x1[(size_t)MAXN * HID];      // relu(ln(x1acc))
__device__ float g_x2acc[(size_t)MAXN * DIN];   // layer-2 accumulator
__device__ int   g_esorted[MAXE];               // edge ids grouped by relation
__device__ int   g_cnt[RNUM];
__device__ int   g_off[RNUM + 1];
__device__ int   g_cursor[RNUM];
__device__ int   g_tileoff[RNUM + 1];

// ---------------- zero accumulators + counters ------------------------------
__global__ void k_zero(int N) {
    int stride = gridDim.x * blockDim.x;
    int i = blockIdx.x * blockDim.x + threadIdx.x;
    float4 z = make_float4(0.f, 0.f, 0.f, 0.f);
    int n1 = N * (HID / 4);
    for (int k = i; k < n1; k += stride) ((float4*)g_x1acc)[k] = z;
    int n2 = N * (DIN / 4);
    for (int k = i; k < n2; k += stride) ((float4*)g_x2acc)[k] = z;
    if (blockIdx.x == 0 && threadIdx.x < RNUM) g_cnt[threadIdx.x] = 0;
}

// ---------------- relation histogram ----------------------------------------
__global__ void k_hist(const int* __restrict__ et, int E) {
    __shared__ int s[RNUM];
    if (threadIdx.x < RNUM) s[threadIdx.x] = 0;
    __syncthreads();
    int stride = gridDim.x * blockDim.x;
    for (int i = blockIdx.x * blockDim.x + threadIdx.x; i < E; i += stride)
        atomicAdd(&s[et[i]], 1);
    __syncthreads();
    if (threadIdx.x < RNUM && s[threadIdx.x]) atomicAdd(&g_cnt[threadIdx.x], s[threadIdx.x]);
}

// ---------------- prefix sums (tiny) ----------------------------------------
__global__ void k_scan() {
    if (threadIdx.x == 0 && blockIdx.x == 0) {
        int o = 0, t = 0;
        for (int r = 0; r < RNUM; ++r) {
            g_off[r] = o; g_cursor[r] = o; g_tileoff[r] = t;
            o += g_cnt[r];
            t += (g_cnt[r] + 63) >> 6;
        }
        g_off[RNUM] = o; g_tileoff[RNUM] = t;
    }
}

// ---------------- bucket edges by relation ----------------------------------
__global__ void k_bucket(const int* __restrict__ et, int E) {
    __shared__ int lcnt[RNUM], lbase[RNUM];
    int e = blockIdx.x * 256 + threadIdx.x;
    if (threadIdx.x < RNUM) lcnt[threadIdx.x] = 0;
    __syncthreads();
    int r = 0, rank = 0;
    if (e < E) { r = et[e]; rank = atomicAdd(&lcnt[r], 1); }
    __syncthreads();
    if (threadIdx.x < RNUM && lcnt[threadIdx.x])
        lbase[threadIdx.x] = atomicAdd(&g_cursor[threadIdx.x], lcnt[threadIdx.x]);
    __syncthreads();
    if (e < E) g_esorted[lbase[r] + rank] = e;
}

// ---------------- layer-1 gather-GEMM-scatter -------------------------------
// Tile: 64 edges x 128 out, K = 64.  SMEM: A^T (64 x pitch65), W (64 x 128).
#define PA1 65
__global__ void __launch_bounds__(256) k_gemm1(
    const int* __restrict__ nid, const int* __restrict__ eidx,
    const float* __restrict__ emb, const float* __restrict__ W1, int E) {
    extern __shared__ float sm[];
    float* At = sm;                        // 64*PA1
    float* Ws = sm + DIN * PA1;            // 64*128
    int*   sdst = (int*)(Ws + DIN * HID);  // 64
    __shared__ int sinfo[3];

    int b = blockIdx.x;
    if (b >= g_tileoff[RNUM]) return;
    int tid = threadIdx.x;
    if (tid == 0) {
        int r = 0;
        while (g_tileoff[r + 1] <= b) ++r;
        int es = g_off[r] + (b - g_tileoff[r]) * 64;
        sinfo[0] = r; sinfo[1] = es;
        sinfo[2] = min(64, g_off[r + 1] - es);
    }
    __syncthreads();
    int r = sinfo[0], estart = sinfo[1], M = sinfo[2];

    // stage W1[r]  (64x128 f32, coalesced, no transpose)
    const float4* Wr = (const float4*)(W1 + (size_t)r * DIN * HID);
    #pragma unroll
    for (int i = 0; i < 8; ++i) ((float4*)Ws)[tid + 256 * i] = Wr[tid + 256 * i];

    // gather + transpose A: edge = tid>>2, quarter = tid&3 (16 floats each)
    {
        int e = tid >> 2, p = tid & 3;
        bool valid = e < M;
        const float* rowp = emb;
        if (valid) {
            int ei = g_esorted[estart + e];
            int s = eidx[ei];
            rowp = emb + (size_t)nid[s] * DIN;
            if (p == 0) sdst[e] = eidx[E + ei];
        }
        #pragma unroll
        for (int q = 0; q < 4; ++q) {
            float4 v = valid ? ((const float4*)rowp)[p * 4 + q]
                             : make_float4(0.f, 0.f, 0.f, 0.f);
            int d = (p * 4 + q) * 4;
            At[(d + 0) * PA1 + e] = v.x;
            At[(d + 1) * PA1 + e] = v.y;
            At[(d + 2) * PA1 + e] = v.z;
            At[(d + 3) * PA1 + e] = v.w;
        }
    }
    __syncthreads();

    int ti = tid & 15, tj = tid >> 4;   // 4 edges x 8 h per thread
    float acc[4][8];
    #pragma unroll
    for (int i = 0; i < 4; ++i)
        #pragma unroll
        for (int j = 0; j < 8; ++j) acc[i][j] = 0.f;

    const float* Ap = At + 4 * ti;
    const float* Wp = Ws + 8 * tj;
    #pragma unroll 8
    for (int d = 0; d < DIN; ++d) {
        float a0 = Ap[d * PA1 + 0], a1 = Ap[d * PA1 + 1];
        float a2 = Ap[d * PA1 + 2], a3 = Ap[d * PA1 + 3];
        float4 w0 = *(const float4*)(Wp + d * HID);
        float4 w1 = *(const float4*)(Wp + d * HID + 4);
        float w[8] = {w0.x, w0.y, w0.z, w0.w, w1.x, w1.y, w1.z, w1.w};
        #pragma unroll
        for (int j = 0; j < 8; ++j) {
            acc[0][j] += a0 * w[j];
            acc[1][j] += a1 * w[j];
            acc[2][j] += a2 * w[j];
            acc[3][j] += a3 * w[j];
        }
    }

    #pragma unroll
    for (int i = 0; i < 4; ++i) {
        int e = 4 * ti + i;
        if (e < M) {
            float* base = g_x1acc + (size_t)sdst[e] * HID + 8 * tj;
            #pragma unroll
            for (int j = 0; j < 8; ++j) atomicAdd(base + j, acc[i][j]);
        }
    }
}

// ---------------- LN1 + ReLU -------------------------------------------------
__global__ void k_ln1(const float* __restrict__ g, const float* __restrict__ bb, int N) {
    int w = (blockIdx.x * blockDim.x + threadIdx.x) >> 5;
    int lane = threadIdx.x & 31;
    if (w >= N) return;
    float4 v = ((const float4*)(g_x1acc + (size_t)w * HID))[lane];
    float s = v.x + v.y + v.z + v.w;
    #pragma unroll
    for (int o = 16; o; o >>= 1) s += __shfl_xor_sync(0xffffffffu, s, o);
    float mu = s * (1.f / HID);
    float dx = v.x - mu, dy = v.y - mu, dz = v.z - mu, dw = v.w - mu;
    float q = dx * dx + dy * dy + dz * dz + dw * dw;
    #pragma unroll
    for (int o = 16; o; o >>= 1) q += __shfl_xor_sync(0xffffffffu, q, o);
    float inv = rsqrtf(q * (1.f / HID) + 1e-5f);
    float4 gv = ((const float4*)g)[lane];
    float4 bv = ((const float4*)bb)[lane];
    float4 o4;
    o4.x = fmaxf(dx * inv * gv.x + bv.x, 0.f);
    o4.y = fmaxf(dy * inv * gv.y + bv.y, 0.f);
    o4.z = fmaxf(dz * inv * gv.z + bv.z, 0.f);
    o4.w = fmaxf(dw * inv * gv.w + bv.w, 0.f);
    ((float4*)(g_x1 + (size_t)w * HID))[lane] = o4;
}

// ---------------- layer-2 gather-GEMM-scatter -------------------------------
// Tile: 64 edges x 64 out, K = 128.  SMEM: A^T (128 x pitch65), W (128 x 64).
#define PA2 65
__global__ void __launch_bounds__(256) k_gemm2(
    const int* __restrict__ eidx, const float* __restrict__ W2, int E) {
    extern __shared__ float sm[];
    float* At = sm;                        // 128*PA2
    float* Ws = sm + HID * PA2;            // 128*64
    int*   sdst = (int*)(Ws + HID * DIN);  // 64
    __shared__ int sinfo[3];

    int b = blockIdx.x;
    if (b >= g_tileoff[RNUM]) return;
    int tid = threadIdx.x;
    if (tid == 0) {
        int r = 0;
        while (g_tileoff[r + 1] <= b) ++r;
        int es = g_off[r] + (b - g_tileoff[r]) * 64;
        sinfo[0] = r; sinfo[1] = es;
        sinfo[2] = min(64, g_off[r + 1] - es);
    }
    __syncthreads();
    int r = sinfo[0], estart = sinfo[1], M = sinfo[2];

    // stage W2[r]  (128x64 f32)
    const float4* Wr = (const float4*)(W2 + (size_t)r * HID * DIN);
    #pragma unroll
    for (int i = 0; i < 8; ++i) ((float4*)Ws)[tid + 256 * i] = Wr[tid + 256 * i];

    // gather + transpose A rows (128 floats each) from g_x1
    {
        int e = tid >> 2, p = tid & 3;   // 32 floats per (e,p)
        bool valid = e < M;
        const float* rowp = g_x1;
        if (valid) {
            int ei = g_esorted[estart + e];
            int s = eidx[ei];
            rowp = g_x1 + (size_t)s * HID;
            if (p == 0) sdst[e] = eidx[E + ei];
        }
        #pragma unroll
        for (int q = 0; q < 8; ++q) {
            float4 v = valid ? ((const float4*)rowp)[p * 8 + q]
                             : make_float4(0.f, 0.f, 0.f, 0.f);
            int d = (p * 8 + q) * 4;
            At[(d + 0) * PA2 + e] = v.x;
            At[(d + 1) * PA2 + e] = v.y;
            At[(d + 2) * PA2 + e] = v.z;
            At[(d + 3) * PA2 + e] = v.w;
        }
    }
    __syncthreads();

    int ti = tid & 15, tj = tid >> 4;   // 4 edges x 4 out per thread
    float acc[4][4];
    #pragma unroll
    for (int i = 0; i < 4; ++i)
        #pragma unroll
        for (int j = 0; j < 4; ++j) acc[i][j] = 0.f;

    const float* Ap = At + 4 * ti;
    const float* Wp = Ws + 4 * tj;
    #pragma unroll 8
    for (int k = 0; k < HID; ++k) {
        float a0 = Ap[k * PA2 + 0], a1 = Ap[k * PA2 + 1];
        float a2 = Ap[k * PA2 + 2], a3 = Ap[k * PA2 + 3];
        float4 w = *(const float4*)(Wp + k * DIN);
        float wv[4] = {w.x, w.y, w.z, w.w};
        #pragma unroll
        for (int j = 0; j < 4; ++j) {
            acc[0][j] += a0 * wv[j];
            acc[1][j] += a1 * wv[j];
            acc[2][j] += a2 * wv[j];
            acc[3][j] += a3 * wv[j];
        }
    }

    #pragma unroll
    for (int i = 0; i < 4; ++i) {
        int e = 4 * ti + i;
        if (e < M) {
            float* base = g_x2acc + (size_t)sdst[e] * DIN + 4 * tj;
            #pragma unroll
            for (int j = 0; j < 4; ++j) atomicAdd(base + j, acc[i][j]);
        }
    }
}

// ---------------- LN2 + residual --------------------------------------------
__global__ void k_ln2res(const int* __restrict__ nid, const float* __restrict__ emb,
                         const float* __restrict__ g, const float* __restrict__ bb,
                         float* __restrict__ out, int N) {
    int w = (blockIdx.x * blockDim.x + threadIdx.x) >> 5;
    int lane = threadIdx.x & 31;
    if (w >= N) return;
    float2 v = ((const float2*)(g_x2acc + (size_t)w * DIN))[lane];
    float s = v.x + v.y;
    #pragma unroll
    for (int o = 16; o; o >>= 1) s += __shfl_xor_sync(0xffffffffu, s, o);
    float mu = s * (1.f / DIN);
    float dx = v.x - mu, dy = v.y - mu;
    float q = dx * dx + dy * dy;
    #pragma unroll
    for (int o = 16; o; o >>= 1) q += __shfl_xor_sync(0xffffffffu, q, o);
    float inv = rsqrtf(q * (1.f / DIN) + 1e-5f);
    float2 gv = ((const float2*)g)[lane];
    float2 bv = ((const float2*)bb)[lane];
    float2 xr = ((const float2*)(emb + (size_t)nid[w] * DIN))[lane];
    float2 o2;
    o2.x = dx * inv * gv.x + bv.x + xr.x;
    o2.y = dy * inv * gv.y + bv.y + xr.y;
    ((float2*)(out + (size_t)w * DIN))[lane] = o2;
}

// ---------------- launch -----------------------------------------------------
extern "C" void kernel_launch(void* const* d_in, const int* in_sizes, int n_in,
                              void* d_out, int out_size) {
    const int*   nid   = (const int*)d_in[0];
    const int*   eidx  = (const int*)d_in[1];   // [2,E]: row0 src, row1 dst
    const int*   etype = (const int*)d_in[2];
    const float* emb   = (const float*)d_in[3];
    const float* W1    = (const float*)d_in[4];
    const float* W2    = (const float*)d_in[5];
    const float* ln1g  = (const float*)d_in[6];
    const float* ln1b  = (const float*)d_in[7];
    const float* ln2g  = (const float*)d_in[8];
    const float* ln2b  = (const float*)d_in[9];
    float* out = (float*)d_out;

    int N = in_sizes[0];
    int E = in_sizes[2];

    constexpr int smem1 = (DIN * PA1 + DIN * HID) * 4 + 64 * 4;   // ~49.9 KB
    constexpr int smem2 = (HID * PA2 + HID * DIN) * 4 + 64 * 4;   // ~66.3 KB
    cudaFuncSetAttribute(k_gemm1, cudaFuncAttributeMaxDynamicSharedMemorySize, smem1);
    cudaFuncSetAttribute(k_gemm2, cudaFuncAttributeMaxDynamicSharedMemorySize, smem2);

    int tiles = (E + 63) / 64 + RNUM;   // upper bound on total tiles

    k_zero<<<512, 256>>>(N);
    k_hist<<<512, 256>>>(etype, E);
    k_scan<<<1, 32>>>();
    k_bucket<<<(E + 255) / 256, 256>>>(etype, E);
    k_gemm1<<<tiles, 256, smem1>>>(nid, eidx, emb, W1, E);
    k_ln1<<<(N * 32 + 255) / 256, 256>>>(ln1g, ln1b, N);
    k_gemm2<<<tiles, 256, smem2>>>(eidx, W2, E);
    k_ln2res<<<(N * 32 + 255) / 256, 256>>>(nid, emb, ln2g, ln2b, out, N);
}

// round 2
// speedup vs baseline: 2.3765x; 2.3765x over previous
#include <cuda_runtime.h>
#include <cuda_bf16.h>
#include <cstdint>

#define MAXN 50000
#define MAXE 600000
#define RNUM 16
#define DIN  64
#define HID  128

// ---------------- scratch ----------------------------------------------------
__device__ float g_x1acc[(size_t)MAXN * HID];
__device__ float g_x2acc[(size_t)MAXN * DIN];
__device__ __nv_bfloat16 g_embh[(size_t)MAXN * DIN];
__device__ __nv_bfloat16 g_embl[(size_t)MAXN * DIN];
__device__ __nv_bfloat16 g_x1h[(size_t)MAXN * HID];
__device__ __nv_bfloat16 g_x1l[(size_t)MAXN * HID];
__device__ __nv_bfloat16 g_w1h[RNUM * DIN * HID];
__device__ __nv_bfloat16 g_w1l[RNUM * DIN * HID];
__device__ __nv_bfloat16 g_w2h[RNUM * HID * DIN];
__device__ __nv_bfloat16 g_w2l[RNUM * HID * DIN];
__device__ int g_esorted[MAXE];
__device__ int g_cnt[RNUM];
__device__ int g_off[RNUM + 1];
__device__ int g_cursor[RNUM];
__device__ int g_tileoff[RNUM + 1];

// ---------------- PTX helpers ------------------------------------------------
__device__ __forceinline__ uint32_t smem_u32(const void* p) {
    return (uint32_t)__cvta_generic_to_shared(p);
}
__device__ __forceinline__ void ldsm_x4(uint32_t* r, uint32_t a) {
    asm volatile("ldmatrix.sync.aligned.m8n8.x4.shared.b16 {%0,%1,%2,%3}, [%4];\n"
                 : "=r"(r[0]), "=r"(r[1]), "=r"(r[2]), "=r"(r[3]) : "r"(a));
}
__device__ __forceinline__ void ldsm_x4t(uint32_t* r, uint32_t a) {
    asm volatile("ldmatrix.sync.aligned.m8n8.x4.trans.shared.b16 {%0,%1,%2,%3}, [%4];\n"
                 : "=r"(r[0]), "=r"(r[1]), "=r"(r[2]), "=r"(r[3]) : "r"(a));
}
__device__ __forceinline__ void mma_bf16(float* c, const uint32_t* a, uint32_t b0, uint32_t b1) {
    asm volatile("mma.sync.aligned.m16n8k16.row.col.f32.bf16.bf16.f32 "
                 "{%0,%1,%2,%3},{%4,%5,%6,%7},{%8,%9},{%0,%1,%2,%3};\n"
                 : "+f"(c[0]), "+f"(c[1]), "+f"(c[2]), "+f"(c[3])
                 : "r"(a[0]), "r"(a[1]), "r"(a[2]), "r"(a[3]), "r"(b0), "r"(b1));
}
__device__ __forceinline__ void split_bf16(float v, __nv_bfloat16& h, __nv_bfloat16& l) {
    h = __float2bfloat16(v);
    l = __float2bfloat16(v - __bfloat162float(h));
}

// ---------------- prep: zero + convert weights/emb ---------------------------
__global__ void k_prep(const float* __restrict__ emb, const float* __restrict__ W1,
                       const float* __restrict__ W2, int N) {
    int stride = gridDim.x * blockDim.x;
    int i = blockIdx.x * blockDim.x + threadIdx.x;
    float4 z = make_float4(0.f, 0.f, 0.f, 0.f);
    int n1 = N * (HID / 4);
    for (int k = i; k < n1; k += stride) ((float4*)g_x1acc)[k] = z;
    int n2 = N * (DIN / 4);
    for (int k = i; k < n2; k += stride) ((float4*)g_x2acc)[k] = z;
    int ne = N * DIN;
    for (int k = i; k < ne; k += stride) split_bf16(emb[k], g_embh[k], g_embl[k]);
    for (int k = i; k < RNUM * DIN * HID; k += stride) split_bf16(W1[k], g_w1h[k], g_w1l[k]);
    for (int k = i; k < RNUM * HID * DIN; k += stride) split_bf16(W2[k], g_w2h[k], g_w2l[k]);
    if (blockIdx.x == 0 && threadIdx.x < RNUM) g_cnt[threadIdx.x] = 0;
}

// ---------------- histogram / scan / bucket ----------------------------------
__global__ void k_hist(const int* __restrict__ et, int E) {
    __shared__ int s[RNUM];
    if (threadIdx.x < RNUM) s[threadIdx.x] = 0;
    __syncthreads();
    int stride = gridDim.x * blockDim.x;
    for (int i = blockIdx.x * blockDim.x + threadIdx.x; i < E; i += stride)
        atomicAdd(&s[et[i]], 1);
    __syncthreads();
    if (threadIdx.x < RNUM && s[threadIdx.x]) atomicAdd(&g_cnt[threadIdx.x], s[threadIdx.x]);
}
__global__ void k_scan() {
    if (threadIdx.x == 0 && blockIdx.x == 0) {
        int o = 0, t = 0;
        for (int r = 0; r < RNUM; ++r) {
            g_off[r] = o; g_cursor[r] = o; g_tileoff[r] = t;
            o += g_cnt[r];
            t += (g_cnt[r] + 63) >> 6;
        }
        g_off[RNUM] = o; g_tileoff[RNUM] = t;
    }
}
__global__ void k_bucket(const int* __restrict__ et, int E) {
    __shared__ int lcnt[RNUM], lbase[RNUM];
    int e = blockIdx.x * 256 + threadIdx.x;
    if (threadIdx.x < RNUM) lcnt[threadIdx.x] = 0;
    __syncthreads();
    int r = 0, rank = 0;
    if (e < E) { r = et[e]; rank = atomicAdd(&lcnt[r], 1); }
    __syncthreads();
    if (threadIdx.x < RNUM && lcnt[threadIdx.x])
        lbase[threadIdx.x] = atomicAdd(&g_cursor[threadIdx.x], lcnt[threadIdx.x]);
    __syncthreads();
    if (e < E) g_esorted[lbase[r] + rank] = e;
}

// ---------------- layer-1: 64x128x64 tile, bf16x3 MMA ------------------------
#define PA1 72
#define PW1 136
#define PC1 132
// smem: Ah[64*72] Al[64*72] Wh[64*136] Wl[64*136] | Cs aliases front | sdst tail
#define SM1_AL (64 * PA1)
#define SM1_WH (2 * 64 * PA1)
#define SM1_WL (2 * 64 * PA1 + 64 * PW1)
#define SM1_END (2 * 64 * PA1 + 2 * 64 * PW1)
#define SMEM1_BYTES (SM1_END * 2 + 64 * 4)

__global__ void __launch_bounds__(256) k_gemm1(
    const int* __restrict__ nid, const int* __restrict__ eidx, int E) {
    extern __shared__ __nv_bfloat16 sm[];
    __nv_bfloat16* Ah = sm;
    __nv_bfloat16* Al = sm + SM1_AL;
    __nv_bfloat16* Wh = sm + SM1_WH;
    __nv_bfloat16* Wl = sm + SM1_WL;
    float* Cs = (float*)sm;
    int* sdst = (int*)(sm + SM1_END);
    __shared__ int sinfo[3];

    int b = blockIdx.x;
    if (b >= g_tileoff[RNUM]) return;
    int tid = threadIdx.x;
    if (tid == 0) {
        int r = 0;
        while (g_tileoff[r + 1] <= b) ++r;
        int es = g_off[r] + (b - g_tileoff[r]) * 64;
        sinfo[0] = r; sinfo[1] = es; sinfo[2] = min(64, g_off[r + 1] - es);
    }
    __syncthreads();
    int r = sinfo[0], estart = sinfo[1], M = sinfo[2];

    // stage W1[r] hi/lo: thread -> row=t>>2 (64), seg=t&3 (32 elems)
    {
        int row = tid >> 2, seg = tid & 3;
        size_t src = ((size_t)r * DIN + row) * HID + seg * 32;
        const uint4* sh = (const uint4*)(g_w1h + src);
        const uint4* sl = (const uint4*)(g_w1l + src);
        uint4* dh = (uint4*)(Wh + row * PW1 + seg * 32);
        uint4* dl = (uint4*)(Wl + row * PW1 + seg * 32);
        #pragma unroll
        for (int q = 0; q < 4; ++q) { dh[q] = sh[q]; dl[q] = sl[q]; }
    }
    // gather A hi/lo: edge=t>>2, p=t&3 covers 16 elems
    {
        int e = tid >> 2, p = tid & 3;
        bool valid = e < M;
        int srow = 0;
        if (valid) {
            int ei = g_esorted[estart + e];
            srow = nid[eidx[ei]];
            if (p == 0) sdst[e] = eidx[E + ei];
        }
        uint4 z4 = make_uint4(0, 0, 0, 0);
        const uint4* sh = (const uint4*)(g_embh + (size_t)srow * DIN) + p * 2;
        const uint4* sl = (const uint4*)(g_embl + (size_t)srow * DIN) + p * 2;
        uint4* dh = (uint4*)(Ah + e * PA1 + p * 16);
        uint4* dl = (uint4*)(Al + e * PA1 + p * 16);
        #pragma unroll
        for (int q = 0; q < 2; ++q) {
            dh[q] = valid ? sh[q] : z4;
            dl[q] = valid ? sl[q] : z4;
        }
    }
    __syncthreads();

    int wid = tid >> 5, lane = tid & 31;
    int wm = wid & 1, wn = wid >> 1;          // 2x4 warp grid
    int mbase = 32 * wm, nbase = 32 * wn;

    uint32_t aOffH = smem_u32(Ah) + (((mbase + (lane & 15)) * PA1 + 8 * (lane >> 4)) << 1);
    uint32_t aOffL = aOffH + (SM1_AL << 1);
    uint32_t bOffH = smem_u32(Wh) +
        (((((lane & 7) + 8 * ((lane >> 3) & 1)) * PW1) + nbase + 8 * (lane >> 4)) << 1);
    uint32_t bOffL = bOffH + ((SM1_WL - SM1_WH) << 1);

    float c[2][4][4];
    #pragma unroll
    for (int mt = 0; mt < 2; ++mt)
        #pragma unroll
        for (int j = 0; j < 4; ++j)
            #pragma unroll
            for (int q = 0; q < 4; ++q) c[mt][j][q] = 0.f;

    #pragma unroll
    for (int ks = 0; ks < 4; ++ks) {
        int kk = ks * 16;
        uint32_t ah[2][4], al[2][4], bh[2][4], bl[2][4];
        #pragma unroll
        for (int mt = 0; mt < 2; ++mt) {
            ldsm_x4(ah[mt], aOffH + ((16 * mt * PA1 + kk) << 1));
            ldsm_x4(al[mt], aOffL + ((16 * mt * PA1 + kk) << 1));
        }
        #pragma unroll
        for (int p = 0; p < 2; ++p) {
            ldsm_x4t(bh[p], bOffH + ((kk * PW1) << 1) + p * 32);
            ldsm_x4t(bl[p], bOffL + ((kk * PW1) << 1) + p * 32);
        }
        #pragma unroll
        for (int mt = 0; mt < 2; ++mt)
            #pragma unroll
            for (int j = 0; j < 4; ++j) {
                int p = j >> 1, w = j & 1;
                mma_bf16(c[mt][j], ah[mt], bh[p][2 * w], bh[p][2 * w + 1]);
                mma_bf16(c[mt][j], ah[mt], bl[p][2 * w], bl[p][2 * w + 1]);
                mma_bf16(c[mt][j], al[mt], bh[p][2 * w], bh[p][2 * w + 1]);
            }
    }
    __syncthreads();   // A/W dead; reuse as Cs

    #pragma unroll
    for (int mt = 0; mt < 2; ++mt) {
        int row0 = mbase + 16 * mt + (lane >> 2);
        #pragma unroll
        for (int j = 0; j < 4; ++j) {
            int col = nbase + 8 * j + 2 * (lane & 3);
            *(float2*)&Cs[row0 * PC1 + col]       = make_float2(c[mt][j][0], c[mt][j][1]);
            *(float2*)&Cs[(row0 + 8) * PC1 + col] = make_float2(c[mt][j][2], c[mt][j][3]);
        }
    }
    __syncthreads();

    // coalesced scatter: warp w -> rows 8w..8w+7
    #pragma unroll
    for (int i = 0; i < 8; ++i) {
        int row = 8 * wid + i;
        if (row < M) {
            float* base = g_x1acc + (size_t)sdst[row] * HID;
            const float* cr = Cs + row * PC1;
            #pragma unroll
            for (int q = 0; q < 4; ++q)
                atomicAdd(base + lane + 32 * q, cr[lane + 32 * q]);
        }
    }
}

// ---------------- LN1 + ReLU -> bf16 hi/lo -----------------------------------
__global__ void k_ln1(const float* __restrict__ g, const float* __restrict__ bb, int N) {
    int w = (blockIdx.x * blockDim.x + threadIdx.x) >> 5;
    int lane = threadIdx.x & 31;
    if (w >= N) return;
    float4 v = ((const float4*)(g_x1acc + (size_t)w * HID))[lane];
    float s = v.x + v.y + v.z + v.w;
    #pragma unroll
    for (int o = 16; o; o >>= 1) s += __shfl_xor_sync(0xffffffffu, s, o);
    float mu = s * (1.f / HID);
    float dx = v.x - mu, dy = v.y - mu, dz = v.z - mu, dw = v.w - mu;
    float q = dx * dx + dy * dy + dz * dz + dw * dw;
    #pragma unroll
    for (int o = 16; o; o >>= 1) q += __shfl_xor_sync(0xffffffffu, q, o);
    float inv = rsqrtf(q * (1.f / HID) + 1e-5f);
    float4 gv = ((const float4*)g)[lane];
    float4 bv = ((const float4*)bb)[lane];
    float o0 = fmaxf(dx * inv * gv.x + bv.x, 0.f);
    float o1 = fmaxf(dy * inv * gv.y + bv.y, 0.f);
    float o2 = fmaxf(dz * inv * gv.z + bv.z, 0.f);
    float o3 = fmaxf(dw * inv * gv.w + bv.w, 0.f);
    __nv_bfloat16 h[4], l[4];
    split_bf16(o0, h[0], l[0]); split_bf16(o1, h[1], l[1]);
    split_bf16(o2, h[2], l[2]); split_bf16(o3, h[3], l[3]);
    ((uint2*)(g_x1h + (size_t)w * HID))[lane] = *(uint2*)h;
    ((uint2*)(g_x1l + (size_t)w * HID))[lane] = *(uint2*)l;
}

// ---------------- layer-2: 64x64x128 tile, bf16x3 MMA ------------------------
#define PA2 136
#define PW2 72
#define PC2 68
#define SM2_AL (64 * PA2)
#define SM2_WH (2 * 64 * PA2)
#define SM2_WL (2 * 64 * PA2 + 128 * PW2)
#define SM2_END (2 * 64 * PA2 + 2 * 128 * PW2)
#define SMEM2_BYTES (SM2_END * 2 + 64 * 4)

__global__ void __launch_bounds__(256) k_gemm2(const int* __restrict__ eidx, int E) {
    extern __shared__ __nv_bfloat16 sm[];
    __nv_bfloat16* Ah = sm;
    __nv_bfloat16* Al = sm + SM2_AL;
    __nv_bfloat16* Wh = sm + SM2_WH;
    __nv_bfloat16* Wl = sm + SM2_WL;
    float* Cs = (float*)sm;
    int* sdst = (int*)(sm + SM2_END);
    __shared__ int sinfo[3];

    int b = blockIdx.x;
    if (b >= g_tileoff[RNUM]) return;
    int tid = threadIdx.x;
    if (tid == 0) {
        int r = 0;
        while (g_tileoff[r + 1] <= b) ++r;
        int es = g_off[r] + (b - g_tileoff[r]) * 64;
        sinfo[0] = r; sinfo[1] = es; sinfo[2] = min(64, g_off[r + 1] - es);
    }
    __syncthreads();
    int r = sinfo[0], estart = sinfo[1], M = sinfo[2];

    // stage W2[r]: row=t>>1 (128), half=t&1 (32 elems)
    {
        int row = tid >> 1, half = tid & 1;
        size_t src = ((size_t)r * HID + row) * DIN + half * 32;
        const uint4* sh = (const uint4*)(g_w2h + src);
        const uint4* sl = (const uint4*)(g_w2l + src);
        uint4* dh = (uint4*)(Wh + row * PW2 + half * 32);
        uint4* dl = (uint4*)(Wl + row * PW2 + half * 32);
        #pragma unroll
        for (int q = 0; q < 4; ++q) { dh[q] = sh[q]; dl[q] = sl[q]; }
    }
    // gather A: edge=t>>2, p=t&3 covers 32 elems
    {
        int e = tid >> 2, p = tid & 3;
        bool valid = e < M;
        int srow = 0;
        if (valid) {
            int ei = g_esorted[estart + e];
            srow = eidx[ei];
            if (p == 0) sdst[e] = eidx[E + ei];
        }
        uint4 z4 = make_uint4(0, 0, 0, 0);
        const uint4* sh = (const uint4*)(g_x1h + (size_t)srow * HID) + p * 4;
        const uint4* sl = (const uint4*)(g_x1l + (size_t)srow * HID) + p * 4;
        uint4* dh = (uint4*)(Ah + e * PA2 + p * 32);
        uint4* dl = (uint4*)(Al + e * PA2 + p * 32);
        #pragma unroll
        for (int q = 0; q < 4; ++q) {
            dh[q] = valid ? sh[q] : z4;
            dl[q] = valid ? sl[q] : z4;
        }
    }
    __syncthreads();

    int wid = tid >> 5, lane = tid & 31;
    int wm = wid & 1, wn = wid >> 1;          // rows 32*wm, cols 16*wn
    int mbase = 32 * wm, nbase = 16 * wn;

    uint32_t aOffH = smem_u32(Ah) + (((mbase + (lane & 15)) * PA2 + 8 * (lane >> 4)) << 1);
    uint32_t aOffL = aOffH + (SM2_AL << 1);
    uint32_t bOffH = smem_u32(Wh) +
        (((((lane & 7) + 8 * ((lane >> 3) & 1)) * PW2) + nbase + 8 * (lane >> 4)) << 1);
    uint32_t bOffL = bOffH + ((SM2_WL - SM2_WH) << 1);

    float c[2][2][4];
    #pragma unroll
    for (int mt = 0; mt < 2; ++mt)
        #pragma unroll
        for (int j = 0; j < 2; ++j)
            #pragma unroll
            for (int q = 0; q < 4; ++q) c[mt][j][q] = 0.f;

    #pragma unroll
    for (int ks = 0; ks < 8; ++ks) {
        int kk = ks * 16;
        uint32_t ah[2][4], al[2][4], bh[4], bl[4];
        #pragma unroll
        for (int mt = 0; mt < 2; ++mt) {
            ldsm_x4(ah[mt], aOffH + ((16 * mt * PA2 + kk) << 1));
            ldsm_x4(al[mt], aOffL + ((16 * mt * PA2 + kk) << 1));
        }
        ldsm_x4t(bh, bOffH + ((kk * PW2) << 1));
        ldsm_x4t(bl, bOffL + ((kk * PW2) << 1));
        #pragma unroll
        for (int mt = 0; mt < 2; ++mt)
            #pragma unroll
            for (int j = 0; j < 2; ++j) {
                mma_bf16(c[mt][j], ah[mt], bh[2 * j], bh[2 * j + 1]);
                mma_bf16(c[mt][j], ah[mt], bl[2 * j], bl[2 * j + 1]);
                mma_bf16(c[mt][j], al[mt], bh[2 * j], bh[2 * j + 1]);
            }
    }
    __syncthreads();

    #pragma unroll
    for (int mt = 0; mt < 2; ++mt) {
        int row0 = mbase + 16 * mt + (lane >> 2);
        #pragma unroll
        for (int j = 0; j < 2; ++j) {
            int col = nbase + 8 * j + 2 * (lane & 3);
            *(float2*)&Cs[row0 * PC2 + col]       = make_float2(c[mt][j][0], c[mt][j][1]);
            *(float2*)&Cs[(row0 + 8) * PC2 + col] = make_float2(c[mt][j][2], c[mt][j][3]);
        }
    }
    __syncthreads();

    #pragma unroll
    for (int i = 0; i < 8; ++i) {
        int row = 8 * wid + i;
        if (row < M) {
            float* base = g_x2acc + (size_t)sdst[row] * DIN;
            const float* cr = Cs + row * PC2;
            #pragma unroll
            for (int q = 0; q < 2; ++q)
                atomicAdd(base + lane + 32 * q, cr[lane + 32 * q]);
        }
    }
}

// ---------------- LN2 + residual ---------------------------------------------
__global__ void k_ln2res(const int* __restrict__ nid, const float* __restrict__ emb,
                         const float* __restrict__ g, const float* __restrict__ bb,
                         float* __restrict__ out, int N) {
    int w = (blockIdx.x * blockDim.x + threadIdx.x) >> 5;
    int lane = threadIdx.x & 31;
    if (w >= N) return;
    float2 v = ((const float2*)(g_x2acc + (size_t)w * DIN))[lane];
    float s = v.x + v.y;
    #pragma unroll
    for (int o = 16; o; o >>= 1) s += __shfl_xor_sync(0xffffffffu, s, o);
    float mu = s * (1.f / DIN);
    float dx = v.x - mu, dy = v.y - mu;
    float q = dx * dx + dy * dy;
    #pragma unroll
    for (int o = 16; o; o >>= 1) q += __shfl_xor_sync(0xffffffffu, q, o);
    float inv = rsqrtf(q * (1.f / DIN) + 1e-5f);
    float2 gv = ((const float2*)g)[lane];
    float2 bv = ((const float2*)bb)[lane];
    float2 xr = ((const float2*)(emb + (size_t)nid[w] * DIN))[lane];
    float2 o2;
    o2.x = dx * inv * gv.x + bv.x + xr.x;
    o2.y = dy * inv * gv.y + bv.y + xr.y;
    ((float2*)(out + (size_t)w * DIN))[lane] = o2;
}

// ---------------- launch -----------------------------------------------------
extern "C" void kernel_launch(void* const* d_in, const int* in_sizes, int n_in,
                              void* d_out, int out_size) {
    const int*   nid   = (const int*)d_in[0];
    const int*   eidx  = (const int*)d_in[1];
    const int*   etype = (const int*)d_in[2];
    const float* emb   = (const float*)d_in[3];
    const float* W1    = (const float*)d_in[4];
    const float* W2    = (const float*)d_in[5];
    const float* ln1g  = (const float*)d_in[6];
    const float* ln1b  = (const float*)d_in[7];
    const float* ln2g  = (const float*)d_in[8];
    const float* ln2b  = (const float*)d_in[9];
    float* out = (float*)d_out;

    int N = in_sizes[0];
    int E = in_sizes[2];

    cudaFuncSetAttribute(k_gemm1, cudaFuncAttributeMaxDynamicSharedMemorySize, SMEM1_BYTES);
    cudaFuncSetAttribute(k_gemm2, cudaFuncAttributeMaxDynamicSharedMemorySize, SMEM2_BYTES);

    int tiles = (E + 63) / 64 + RNUM;

    k_prep<<<1024, 256>>>(emb, W1, W2, N);
    k_hist<<<512, 256>>>(etype, E);
    k_scan<<<1, 32>>>();
    k_bucket<<<(E + 255) / 256, 256>>>(etype, E);
    k_gemm1<<<tiles, 256, SMEM1_BYTES>>>(nid, eidx, E);
    k_ln1<<<(N * 32 + 255) / 256, 256>>>(ln1g, ln1b, N);
    k_gemm2<<<tiles, 256, SMEM2_BYTES>>>(eidx, E);
    k_ln2res<<<(N * 32 + 255) / 256, 256>>>(nid, emb, ln2g, ln2b, out, N);
}

// round 3
// speedup vs baseline: 2.8419x; 1.1958x over previous
#include <cuda_runtime.h>
#include <cuda_bf16.h>
#include <cstdint>

#define MAXN 50000
#define MAXE 600000
#define RNUM 16
#define DIN  64
#define HID  128

// ---------------- scratch ----------------------------------------------------
__device__ float g_x1acc[(size_t)MAXN * HID];
__device__ float g_x2acc[(size_t)MAXN * DIN];
__device__ __nv_bfloat16 g_embh[(size_t)MAXN * DIN];
__device__ __nv_bfloat16 g_embl[(size_t)MAXN * DIN];
__device__ __nv_bfloat16 g_x1h[(size_t)MAXN * HID];
__device__ __nv_bfloat16 g_x1l[(size_t)MAXN * HID];
__device__ __nv_bfloat16 g_w1h[RNUM * DIN * HID];
__device__ __nv_bfloat16 g_w1l[RNUM * DIN * HID];
__device__ __nv_bfloat16 g_w2h[RNUM * HID * DIN];
__device__ __nv_bfloat16 g_w2l[RNUM * HID * DIN];
__device__ int g_esorted[MAXE];
__device__ int g_cnt[RNUM];
__device__ int g_off[RNUM + 1];
__device__ int g_cursor[RNUM];
__device__ int g_tileoff[RNUM + 1];

// ---------------- PTX helpers ------------------------------------------------
__device__ __forceinline__ uint32_t smem_u32(const void* p) {
    return (uint32_t)__cvta_generic_to_shared(p);
}
__device__ __forceinline__ void ldsm_x4(uint32_t* r, uint32_t a) {
    asm volatile("ldmatrix.sync.aligned.m8n8.x4.shared.b16 {%0,%1,%2,%3}, [%4];\n"
                 : "=r"(r[0]), "=r"(r[1]), "=r"(r[2]), "=r"(r[3]) : "r"(a));
}
__device__ __forceinline__ void ldsm_x4t(uint32_t* r, uint32_t a) {
    asm volatile("ldmatrix.sync.aligned.m8n8.x4.trans.shared.b16 {%0,%1,%2,%3}, [%4];\n"
                 : "=r"(r[0]), "=r"(r[1]), "=r"(r[2]), "=r"(r[3]) : "r"(a));
}
__device__ __forceinline__ void mma_bf16(float* c, const uint32_t* a, uint32_t b0, uint32_t b1) {
    asm volatile("mma.sync.aligned.m16n8k16.row.col.f32.bf16.bf16.f32 "
                 "{%0,%1,%2,%3},{%4,%5,%6,%7},{%8,%9},{%0,%1,%2,%3};\n"
                 : "+f"(c[0]), "+f"(c[1]), "+f"(c[2]), "+f"(c[3])
                 : "r"(a[0]), "r"(a[1]), "r"(a[2]), "r"(a[3]), "r"(b0), "r"(b1));
}
__device__ __forceinline__ void split_bf16(float v, __nv_bfloat16& h, __nv_bfloat16& l) {
    h = __float2bfloat16(v);
    l = __float2bfloat16(v - __bfloat162float(h));
}

// ---------------- prep: zero + convert weights/emb ---------------------------
__global__ void k_prep(const float* __restrict__ emb, const float* __restrict__ W1,
                       const float* __restrict__ W2, int N) {
    int stride = gridDim.x * blockDim.x;
    int i = blockIdx.x * blockDim.x + threadIdx.x;
    float4 z = make_float4(0.f, 0.f, 0.f, 0.f);
    int n1 = N * (HID / 4);
    for (int k = i; k < n1; k += stride) ((float4*)g_x1acc)[k] = z;
    int n2 = N * (DIN / 4);
    for (int k = i; k < n2; k += stride) ((float4*)g_x2acc)[k] = z;
    int ne = N * DIN;
    for (int k = i; k < ne; k += stride) split_bf16(emb[k], g_embh[k], g_embl[k]);
    for (int k = i; k < RNUM * DIN * HID; k += stride) split_bf16(W1[k], g_w1h[k], g_w1l[k]);
    for (int k = i; k < RNUM * HID * DIN; k += stride) split_bf16(W2[k], g_w2h[k], g_w2l[k]);
    if (blockIdx.x == 0 && threadIdx.x < RNUM) g_cnt[threadIdx.x] = 0;
}

// ---------------- histogram / scan / bucket ----------------------------------
__global__ void k_hist(const int* __restrict__ et, int E) {
    __shared__ int s[RNUM];
    if (threadIdx.x < RNUM) s[threadIdx.x] = 0;
    __syncthreads();
    int stride = gridDim.x * blockDim.x;
    for (int i = blockIdx.x * blockDim.x + threadIdx.x; i < E; i += stride)
        atomicAdd(&s[et[i]], 1);
    __syncthreads();
    if (threadIdx.x < RNUM && s[threadIdx.x]) atomicAdd(&g_cnt[threadIdx.x], s[threadIdx.x]);
}
__global__ void k_scan() {
    if (threadIdx.x == 0 && blockIdx.x == 0) {
        int o = 0, t = 0;
        for (int r = 0; r < RNUM; ++r) {
            g_off[r] = o; g_cursor[r] = o; g_tileoff[r] = t;
            o += g_cnt[r];
            t += (g_cnt[r] + 255) >> 8;       // blocks of 256 edges
        }
        g_off[RNUM] = o; g_tileoff[RNUM] = t;
    }
}
__global__ void k_bucket(const int* __restrict__ et, int E) {
    __shared__ int lcnt[RNUM], lbase[RNUM];
    int e = blockIdx.x * 256 + threadIdx.x;
    if (threadIdx.x < RNUM) lcnt[threadIdx.x] = 0;
    __syncthreads();
    int r = 0, rank = 0;
    if (e < E) { r = et[e]; rank = atomicAdd(&lcnt[r], 1); }
    __syncthreads();
    if (threadIdx.x < RNUM && lcnt[threadIdx.x])
        lbase[threadIdx.x] = atomicAdd(&g_cursor[threadIdx.x], lcnt[threadIdx.x]);
    __syncthreads();
    if (e < E) g_esorted[lbase[r] + rank] = e;
}

// ---------------- layer-1: 256 edges/block, 4 sub-tiles of 64x128x64 ---------
#define PA1 72
#define PW1 136
#define PC1 132
// smem (bf16 elems): Wh[64*136] Wl[64*136] | A region (Ah 64*72, Al 64*72),
// Cs (float, 64*132) aliases A region; sdst after Cs.
#define SM1_WL   (64 * PW1)
#define SM1_A    (2 * 64 * PW1)
#define SM1_ALO  (SM1_A + 64 * PA1)
#define SM1_SDST (SM1_A + 64 * PC1 * 2)
#define SMEM1_BYTES ((SM1_SDST + 128) * 2)

__global__ void __launch_bounds__(256) k_gemm1(
    const int* __restrict__ nid, const int* __restrict__ eidx, int E) {
    extern __shared__ __nv_bfloat16 sm[];
    __nv_bfloat16* Wh = sm;
    __nv_bfloat16* Wl = sm + SM1_WL;
    __nv_bfloat16* Ah = sm + SM1_A;
    __nv_bfloat16* Al = sm + SM1_ALO;
    float* Cs = (float*)(sm + SM1_A);
    int* sdst = (int*)(sm + SM1_SDST);
    __shared__ int sinfo[2];

    int b = blockIdx.x;
    if (b >= g_tileoff[RNUM]) return;
    int tid = threadIdx.x;
    int r = 0;
    if (tid == 0) {
        while (g_tileoff[r + 1] <= b) ++r;
        sinfo[0] = g_off[r] + (b - g_tileoff[r]) * 256;
        sinfo[1] = g_off[r + 1];
        // stage relation id via sdst[0] is unsafe; use sinfo packing below
    }
    // broadcast r: recompute cheaply in all threads (tileoff in L2, 16 iters max)
    {
        int rr = 0;
        while (g_tileoff[rr + 1] <= b) ++rr;
        r = rr;
    }
    __syncthreads();
    int base = sinfo[0], rend = sinfo[1];

    // stage W1[r] hi/lo once: row=t>>2 (64), seg=t&3 (32 elems)
    {
        int row = tid >> 2, seg = tid & 3;
        size_t src = ((size_t)r * DIN + row) * HID + seg * 32;
        const uint4* sh = (const uint4*)(g_w1h + src);
        const uint4* sl = (const uint4*)(g_w1l + src);
        uint4* dh = (uint4*)(Wh + row * PW1 + seg * 32);
        uint4* dl = (uint4*)(Wl + row * PW1 + seg * 32);
        #pragma unroll
        for (int q = 0; q < 4; ++q) { dh[q] = sh[q]; dl[q] = sl[q]; }
    }

    int wid = tid >> 5, lane = tid & 31;
    int wm = wid & 1, wn = wid >> 1;
    int mbase = 32 * wm, nbase = 32 * wn;
    uint32_t aOffH = smem_u32(Ah) + (((mbase + (lane & 15)) * PA1 + 8 * (lane >> 4)) << 1);
    uint32_t aOffL = aOffH + ((64 * PA1) << 1);
    uint32_t bOffH = smem_u32(Wh) +
        (((((lane & 7) + 8 * ((lane >> 3) & 1)) * PW1) + nbase + 8 * (lane >> 4)) << 1);
    uint32_t bOffL = bOffH + (SM1_WL << 1);

    for (int sub = 0; sub < 4; ++sub) {
        int estart = base + sub * 64;
        int M = rend - estart;
        if (M <= 0) break;
        if (M > 64) M = 64;
        __syncthreads();   // prev scatter done (Cs aliases A); W staged (first iter)

        // gather A hi/lo: edge=t>>2, p=t&3 covers 16 elems
        {
            int e = tid >> 2, p = tid & 3;
            bool valid = e < M;
            int srow = 0;
            if (valid) {
                int ei = g_esorted[estart + e];
                srow = nid[eidx[ei]];
                if (p == 0) sdst[e] = eidx[E + ei];
            }
            uint4 z4 = make_uint4(0, 0, 0, 0);
            const uint4* sh = (const uint4*)(g_embh + (size_t)srow * DIN) + p * 2;
            const uint4* sl = (const uint4*)(g_embl + (size_t)srow * DIN) + p * 2;
            uint4* dh = (uint4*)(Ah + e * PA1 + p * 16);
            uint4* dl = (uint4*)(Al + e * PA1 + p * 16);
            #pragma unroll
            for (int q = 0; q < 2; ++q) {
                dh[q] = valid ? sh[q] : z4;
                dl[q] = valid ? sl[q] : z4;
            }
        }
        __syncthreads();

        float c[2][4][4];
        #pragma unroll
        for (int mt = 0; mt < 2; ++mt)
            #pragma unroll
            for (int j = 0; j < 4; ++j)
                #pragma unroll
                for (int q = 0; q < 4; ++q) c[mt][j][q] = 0.f;

        #pragma unroll
        for (int ks = 0; ks < 4; ++ks) {
            int kk = ks * 16;
            uint32_t ah[2][4], al[2][4], bh[2][4], bl[2][4];
            #pragma unroll
            for (int mt = 0; mt < 2; ++mt) {
                ldsm_x4(ah[mt], aOffH + ((16 * mt * PA1 + kk) << 1));
                ldsm_x4(al[mt], aOffL + ((16 * mt * PA1 + kk) << 1));
            }
            #pragma unroll
            for (int p = 0; p < 2; ++p) {
                ldsm_x4t(bh[p], bOffH + ((kk * PW1) << 1) + p * 32);
                ldsm_x4t(bl[p], bOffL + ((kk * PW1) << 1) + p * 32);
            }
            #pragma unroll
            for (int mt = 0; mt < 2; ++mt)
                #pragma unroll
                for (int j = 0; j < 4; ++j) {
                    int p = j >> 1, w = j & 1;
                    mma_bf16(c[mt][j], ah[mt], bh[p][2 * w], bh[p][2 * w + 1]);
                    mma_bf16(c[mt][j], ah[mt], bl[p][2 * w], bl[p][2 * w + 1]);
                    mma_bf16(c[mt][j], al[mt], bh[p][2 * w], bh[p][2 * w + 1]);
                }
        }
        __syncthreads();   // A reads done; reuse region as Cs

        #pragma unroll
        for (int mt = 0; mt < 2; ++mt) {
            int row0 = mbase + 16 * mt + (lane >> 2);
            #pragma unroll
            for (int j = 0; j < 4; ++j) {
                int col = nbase + 8 * j + 2 * (lane & 3);
                *(float2*)&Cs[row0 * PC1 + col]       = make_float2(c[mt][j][0], c[mt][j][1]);
                *(float2*)&Cs[(row0 + 8) * PC1 + col] = make_float2(c[mt][j][2], c[mt][j][3]);
            }
        }
        __syncthreads();

        // coalesced v4 scatter: warp w -> rows 8w..8w+7, lane -> one float4
        #pragma unroll
        for (int i = 0; i < 8; ++i) {
            int row = 8 * wid + i;
            if (row < M) {
                float4 v = *(const float4*)&Cs[row * PC1 + 4 * lane];
                atomicAdd((float4*)(g_x1acc + (size_t)sdst[row] * HID) + lane, v);
            }
        }
    }
}

// ---------------- LN1 + ReLU -> bf16 hi/lo -----------------------------------
__global__ void k_ln1(const float* __restrict__ g, const float* __restrict__ bb, int N) {
    int w = (blockIdx.x * blockDim.x + threadIdx.x) >> 5;
    int lane = threadIdx.x & 31;
    if (w >= N) return;
    float4 v = ((const float4*)(g_x1acc + (size_t)w * HID))[lane];
    float s = v.x + v.y + v.z + v.w;
    #pragma unroll
    for (int o = 16; o; o >>= 1) s += __shfl_xor_sync(0xffffffffu, s, o);
    float mu = s * (1.f / HID);
    float dx = v.x - mu, dy = v.y - mu, dz = v.z - mu, dw = v.w - mu;
    float q = dx * dx + dy * dy + dz * dz + dw * dw;
    #pragma unroll
    for (int o = 16; o; o >>= 1) q += __shfl_xor_sync(0xffffffffu, q, o);
    float inv = rsqrtf(q * (1.f / HID) + 1e-5f);
    float4 gv = ((const float4*)g)[lane];
    float4 bv = ((const float4*)bb)[lane];
    float o0 = fmaxf(dx * inv * gv.x + bv.x, 0.f);
    float o1 = fmaxf(dy * inv * gv.y + bv.y, 0.f);
    float o2 = fmaxf(dz * inv * gv.z + bv.z, 0.f);
    float o3 = fmaxf(dw * inv * gv.w + bv.w, 0.f);
    __nv_bfloat16 h[4], l[4];
    split_bf16(o0, h[0], l[0]); split_bf16(o1, h[1], l[1]);
    split_bf16(o2, h[2], l[2]); split_bf16(o3, h[3], l[3]);
    ((uint2*)(g_x1h + (size_t)w * HID))[lane] = *(uint2*)h;
    ((uint2*)(g_x1l + (size_t)w * HID))[lane] = *(uint2*)l;
}

// ---------------- layer-2: 256 edges/block, 4 sub-tiles of 64x64x128 ---------
#define PA2 136
#define PW2 72
#define PC2 68
#define SM2_WL   (128 * PW2)
#define SM2_A    (2 * 128 * PW2)
#define SM2_ALO  (SM2_A + 64 * PA2)
#define SM2_SDST (SM2_A + 2 * 64 * PA2)
#define SMEM2_BYTES ((SM2_SDST + 128) * 2)

__global__ void __launch_bounds__(256) k_gemm2(const int* __restrict__ eidx, int E) {
    extern __shared__ __nv_bfloat16 sm[];
    __nv_bfloat16* Wh = sm;
    __nv_bfloat16* Wl = sm + SM2_WL;
    __nv_bfloat16* Ah = sm + SM2_A;
    __nv_bfloat16* Al = sm + SM2_ALO;
    float* Cs = (float*)(sm + SM2_A);
    int* sdst = (int*)(sm + SM2_SDST);
    __shared__ int sinfo[2];

    int b = blockIdx.x;
    if (b >= g_tileoff[RNUM]) return;
    int tid = threadIdx.x;
    int r = 0;
    if (tid == 0) {
        int rr = 0;
        while (g_tileoff[rr + 1] <= b) ++rr;
        sinfo[0] = g_off[rr] + (b - g_tileoff[rr]) * 256;
        sinfo[1] = g_off[rr + 1];
    }
    {
        int rr = 0;
        while (g_tileoff[rr + 1] <= b) ++rr;
        r = rr;
    }
    __syncthreads();
    int base = sinfo[0], rend = sinfo[1];

    // stage W2[r] once: row=t>>1 (128), half=t&1 (32 elems)
    {
        int row = tid >> 1, half = tid & 1;
        size_t src = ((size_t)r * HID + row) * DIN + half * 32;
        const uint4* sh = (const uint4*)(g_w2h + src);
        const uint4* sl = (const uint4*)(g_w2l + src);
        uint4* dh = (uint4*)(Wh + row * PW2 + half * 32);
        uint4* dl = (uint4*)(Wl + row * PW2 + half * 32);
        #pragma unroll
        for (int q = 0; q < 4; ++q) { dh[q] = sh[q]; dl[q] = sl[q]; }
    }

    int wid = tid >> 5, lane = tid & 31;
    int wm = wid & 1, wn = wid >> 1;
    int mbase = 32 * wm, nbase = 16 * wn;
    uint32_t aOffH = smem_u32(Ah) + (((mbase + (lane & 15)) * PA2 + 8 * (lane >> 4)) << 1);
    uint32_t aOffL = aOffH + ((64 * PA2) << 1);
    uint32_t bOffH = smem_u32(Wh) +
        (((((lane & 7) + 8 * ((lane >> 3) & 1)) * PW2) + nbase + 8 * (lane >> 4)) << 1);
    uint32_t bOffL = bOffH + (SM2_WL << 1);

    for (int sub = 0; sub < 4; ++sub) {
        int estart = base + sub * 64;
        int M = rend - estart;
        if (M <= 0) break;
        if (M > 64) M = 64;
        __syncthreads();

        // gather A: edge=t>>2, p=t&3 covers 32 elems
        {
            int e = tid >> 2, p = tid & 3;
            bool valid = e < M;
            int srow = 0;
            if (valid) {
                int ei = g_esorted[estart + e];
                srow = eidx[ei];
                if (p == 0) sdst[e] = eidx[E + ei];
            }
            uint4 z4 = make_uint4(0, 0, 0, 0);
            const uint4* sh = (const uint4*)(g_x1h + (size_t)srow * HID) + p * 4;
            const uint4* sl = (const uint4*)(g_x1l + (size_t)srow * HID) + p * 4;
            uint4* dh = (uint4*)(Ah + e * PA2 + p * 32);
            uint4* dl = (uint4*)(Al + e * PA2 + p * 32);
            #pragma unroll
            for (int q = 0; q < 4; ++q) {
                dh[q] = valid ? sh[q] : z4;
                dl[q] = valid ? sl[q] : z4;
            }
        }
        __syncthreads();

        float c[2][2][4];
        #pragma unroll
        for (int mt = 0; mt < 2; ++mt)
            #pragma unroll
            for (int j = 0; j < 2; ++j)
                #pragma unroll
                for (int q = 0; q < 4; ++q) c[mt][j][q] = 0.f;

        #pragma unroll
        for (int ks = 0; ks < 8; ++ks) {
            int kk = ks * 16;
            uint32_t ah[2][4], al[2][4], bh[4], bl[4];
            #pragma unroll
            for (int mt = 0; mt < 2; ++mt) {
                ldsm_x4(ah[mt], aOffH + ((16 * mt * PA2 + kk) << 1));
                ldsm_x4(al[mt], aOffL + ((16 * mt * PA2 + kk) << 1));
            }
            ldsm_x4t(bh, bOffH + ((kk * PW2) << 1));
            ldsm_x4t(bl, bOffL + ((kk * PW2) << 1));
            #pragma unroll
            for (int mt = 0; mt < 2; ++mt)
                #pragma unroll
                for (int j = 0; j < 2; ++j) {
                    mma_bf16(c[mt][j], ah[mt], bh[2 * j], bh[2 * j + 1]);
                    mma_bf16(c[mt][j], ah[mt], bl[2 * j], bl[2 * j + 1]);
                    mma_bf16(c[mt][j], al[mt], bh[2 * j], bh[2 * j + 1]);
                }
        }
        __syncthreads();

        #pragma unroll
        for (int mt = 0; mt < 2; ++mt) {
            int row0 = mbase + 16 * mt + (lane >> 2);
            #pragma unroll
            for (int j = 0; j < 2; ++j) {
                int col = nbase + 8 * j + 2 * (lane & 3);
                *(float2*)&Cs[row0 * PC2 + col]       = make_float2(c[mt][j][0], c[mt][j][1]);
                *(float2*)&Cs[(row0 + 8) * PC2 + col] = make_float2(c[mt][j][2], c[mt][j][3]);
            }
        }
        __syncthreads();

        // v4 scatter: 2 rows per warp step (16 lanes each)
        #pragma unroll
        for (int i = 0; i < 4; ++i) {
            int row = 8 * wid + 2 * i + (lane >> 4);
            int c4 = lane & 15;
            if (row < M) {
                float4 v = *(const float4*)&Cs[row * PC2 + 4 * c4];
                atomicAdd((float4*)(g_x2acc + (size_t)sdst[row] * DIN) + c4, v);
            }
        }
    }
}

// ---------------- LN2 + residual ---------------------------------------------
__global__ void k_ln2res(const int* __restrict__ nid, const float* __restrict__ emb,
                         const float* __restrict__ g, const float* __restrict__ bb,
                         float* __restrict__ out, int N) {
    int w = (blockIdx.x * blockDim.x + threadIdx.x) >> 5;
    int lane = threadIdx.x & 31;
    if (w >= N) return;
    float2 v = ((const float2*)(g_x2acc + (size_t)w * DIN))[lane];
    float s = v.x + v.y;
    #pragma unroll
    for (int o = 16; o; o >>= 1) s += __shfl_xor_sync(0xffffffffu, s, o);
    float mu = s * (1.f / DIN);
    float dx = v.x - mu, dy = v.y - mu;
    float q = dx * dx + dy * dy;
    #pragma unroll
    for (int o = 16; o; o >>= 1) q += __shfl_xor_sync(0xffffffffu, q, o);
    float inv = rsqrtf(q * (1.f / DIN) + 1e-5f);
    float2 gv = ((const float2*)g)[lane];
    float2 bv = ((const float2*)bb)[lane];
    float2 xr = ((const float2*)(emb + (size_t)nid[w] * DIN))[lane];
    float2 o2;
    o2.x = dx * inv * gv.x + bv.x + xr.x;
    o2.y = dy * inv * gv.y + bv.y + xr.y;
    ((float2*)(out + (size_t)w * DIN))[lane] = o2;
}

// ---------------- launch -----------------------------------------------------
extern "C" void kernel_launch(void* const* d_in, const int* in_sizes, int n_in,
                              void* d_out, int out_size) {
    const int*   nid   = (const int*)d_in[0];
    const int*   eidx  = (const int*)d_in[1];
    const int*   etype = (const int*)d_in[2];
    const float* emb   = (const float*)d_in[3];
    const float* W1    = (const float*)d_in[4];
    const float* W2    = (const float*)d_in[5];
    const float* ln1g  = (const float*)d_in[6];
    const float* ln1b  = (const float*)d_in[7];
    const float* ln2g  = (const float*)d_in[8];
    const float* ln2b  = (const float*)d_in[9];
    float* out = (float*)d_out;

    int N = in_sizes[0];
    int E = in_sizes[2];

    cudaFuncSetAttribute(k_gemm1, cudaFuncAttributeMaxDynamicSharedMemorySize, SMEM1_BYTES);
    cudaFuncSetAttribute(k_gemm2, cudaFuncAttributeMaxDynamicSharedMemorySize, SMEM2_BYTES);

    int blocks = (E + 255) / 256 + RNUM;   // upper bound on 256-edge blocks

    k_prep<<<1024, 256>>>(emb, W1, W2, N);
    k_hist<<<512, 256>>>(etype, E);
    k_scan<<<1, 32>>>();
    k_bucket<<<(E + 255) / 256, 256>>>(etype, E);
    k_gemm1<<<blocks, 256, SMEM1_BYTES>>>(nid, eidx, E);
    k_ln1<<<(N * 32 + 255) / 256, 256>>>(ln1g, ln1b, N);
    k_gemm2<<<blocks, 256, SMEM2_BYTES>>>(eidx, E);
    k_ln2res<<<(N * 32 + 255) / 256, 256>>>(nid, emb, ln2g, ln2b, out, N);
}

// round 4
// speedup vs baseline: 2.9580x; 1.0408x over previous
#include <cuda_runtime.h>
#include <cuda_bf16.h>
#include <cstdint>

#define MAXN 50000
#define MAXE 600000
#define RNUM 16
#define DIN  64
#define HID  128

// ---------------- scratch ----------------------------------------------------
__device__ float g_x1acc[(size_t)MAXN * HID];
__device__ float g_x2acc[(size_t)MAXN * DIN];
__device__ __nv_bfloat16 g_embh[(size_t)MAXN * DIN];
__device__ __nv_bfloat16 g_embl[(size_t)MAXN * DIN];
__device__ __nv_bfloat16 g_x1h[(size_t)MAXN * HID];
__device__ __nv_bfloat16 g_x1l[(size_t)MAXN * HID];
__device__ __nv_bfloat16 g_w1h[RNUM * DIN * HID];
__device__ __nv_bfloat16 g_w1l[RNUM * DIN * HID];
__device__ __nv_bfloat16 g_w2h[RNUM * HID * DIN];
__device__ __nv_bfloat16 g_w2l[RNUM * HID * DIN];
__device__ int g_esrc1[MAXE];   // emb row of src (nid[src]), relation-sorted
__device__ int g_esrc2[MAXE];   // src node index, relation-sorted
__device__ int g_edst[MAXE];    // dst node index, relation-sorted
__device__ int g_cnt[RNUM];
__device__ int g_off[RNUM + 1];
__device__ int g_cursor[RNUM];
__device__ int g_tileoff[RNUM + 1];

// ---------------- PTX helpers ------------------------------------------------
__device__ __forceinline__ uint32_t smem_u32(const void* p) {
    return (uint32_t)__cvta_generic_to_shared(p);
}
__device__ __forceinline__ void ldsm_x4(uint32_t* r, uint32_t a) {
    asm volatile("ldmatrix.sync.aligned.m8n8.x4.shared.b16 {%0,%1,%2,%3}, [%4];\n"
                 : "=r"(r[0]), "=r"(r[1]), "=r"(r[2]), "=r"(r[3]) : "r"(a));
}
__device__ __forceinline__ void ldsm_x4t(uint32_t* r, uint32_t a) {
    asm volatile("ldmatrix.sync.aligned.m8n8.x4.trans.shared.b16 {%0,%1,%2,%3}, [%4];\n"
                 : "=r"(r[0]), "=r"(r[1]), "=r"(r[2]), "=r"(r[3]) : "r"(a));
}
__device__ __forceinline__ void mma_bf16(float* c, const uint32_t* a, uint32_t b0, uint32_t b1) {
    asm volatile("mma.sync.aligned.m16n8k16.row.col.f32.bf16.bf16.f32 "
                 "{%0,%1,%2,%3},{%4,%5,%6,%7},{%8,%9},{%0,%1,%2,%3};\n"
                 : "+f"(c[0]), "+f"(c[1]), "+f"(c[2]), "+f"(c[3])
                 : "r"(a[0]), "r"(a[1]), "r"(a[2]), "r"(a[3]), "r"(b0), "r"(b1));
}
__device__ __forceinline__ void cpasync16(uint32_t saddr, const void* g) {
    asm volatile("cp.async.cg.shared.global [%0], [%1], 16;\n" :: "r"(saddr), "l"(g));
}
__device__ __forceinline__ void cp_commit() {
    asm volatile("cp.async.commit_group;\n");
}
__device__ __forceinline__ void cp_wait0() {
    asm volatile("cp.async.wait_group 0;\n");
}
__device__ __forceinline__ void red2(float* p, float x, float y) {
    asm volatile("red.global.add.v2.f32 [%0], {%1,%2};\n" :: "l"(p), "f"(x), "f"(y) : "memory");
}
__device__ __forceinline__ void split_bf16(float v, __nv_bfloat16& h, __nv_bfloat16& l) {
    h = __float2bfloat16(v);
    l = __float2bfloat16(v - __bfloat162float(h));
}

// ---------------- prep: zero + convert weights/emb ---------------------------
__global__ void k_prep(const float* __restrict__ emb, const float* __restrict__ W1,
                       const float* __restrict__ W2, int N) {
    int stride = gridDim.x * blockDim.x;
    int i = blockIdx.x * blockDim.x + threadIdx.x;
    float4 z = make_float4(0.f, 0.f, 0.f, 0.f);
    int n1 = N * (HID / 4);
    for (int k = i; k < n1; k += stride) ((float4*)g_x1acc)[k] = z;
    int n2 = N * (DIN / 4);
    for (int k = i; k < n2; k += stride) ((float4*)g_x2acc)[k] = z;
    int ne = N * DIN;
    for (int k = i; k < ne; k += stride) split_bf16(emb[k], g_embh[k], g_embl[k]);
    for (int k = i; k < RNUM * DIN * HID; k += stride) split_bf16(W1[k], g_w1h[k], g_w1l[k]);
    for (int k = i; k < RNUM * HID * DIN; k += stride) split_bf16(W2[k], g_w2h[k], g_w2l[k]);
    if (blockIdx.x == 0 && threadIdx.x < RNUM) g_cnt[threadIdx.x] = 0;
}

// ---------------- histogram / scan / bucket ----------------------------------
__global__ void k_hist(const int* __restrict__ et, int E) {
    __shared__ int s[RNUM];
    if (threadIdx.x < RNUM) s[threadIdx.x] = 0;
    __syncthreads();
    int stride = gridDim.x * blockDim.x;
    for (int i = blockIdx.x * blockDim.x + threadIdx.x; i < E; i += stride)
        atomicAdd(&s[et[i]], 1);
    __syncthreads();
    if (threadIdx.x < RNUM && s[threadIdx.x]) atomicAdd(&g_cnt[threadIdx.x], s[threadIdx.x]);
}
__global__ void k_scan() {
    if (threadIdx.x == 0 && blockIdx.x == 0) {
        int o = 0, t = 0;
        for (int r = 0; r < RNUM; ++r) {
            g_off[r] = o; g_cursor[r] = o; g_tileoff[r] = t;
            o += g_cnt[r];
            t += (g_cnt[r] + 255) >> 8;
        }
        g_off[RNUM] = o; g_tileoff[RNUM] = t;
    }
}
__global__ void k_bucket(const int* __restrict__ et, const int* __restrict__ eidx,
                         const int* __restrict__ nid, int E) {
    __shared__ int lcnt[RNUM], lbase[RNUM];
    int e = blockIdx.x * 256 + threadIdx.x;
    if (threadIdx.x < RNUM) lcnt[threadIdx.x] = 0;
    __syncthreads();
    int r = 0, rank = 0, s = 0, d = 0;
    if (e < E) {
        r = et[e]; s = eidx[e]; d = eidx[E + e];
        rank = atomicAdd(&lcnt[r], 1);
    }
    __syncthreads();
    if (threadIdx.x < RNUM && lcnt[threadIdx.x])
        lbase[threadIdx.x] = atomicAdd(&g_cursor[threadIdx.x], lcnt[threadIdx.x]);
    __syncthreads();
    if (e < E) {
        int pos = lbase[r] + rank;
        g_esrc1[pos] = nid[s];
        g_esrc2[pos] = s;
        g_edst[pos]  = d;
    }
}

// ---------------- layer-1: 256 edges/block, pipelined 64x128x64 sub-tiles ----
#define PA1 72
#define PW1 136
#define SM1_WL   (64 * PW1)
#define SM1_A    (2 * 64 * PW1)
#define SM1_ABUF (2 * 64 * PA1)
#define SMEM1_BYTES ((SM1_A + 2 * SM1_ABUF) * 2)

__global__ void __launch_bounds__(256) k_gemm1() {
    extern __shared__ __nv_bfloat16 sm[];
    __nv_bfloat16* Wh = sm;
    __nv_bfloat16* Wl = sm + SM1_WL;
    __shared__ int sdst[2][64];

    int b = blockIdx.x;
    if (b >= g_tileoff[RNUM]) return;
    int tid = threadIdx.x;
    int r = 0;
    while (g_tileoff[r + 1] <= b) ++r;
    int base = g_off[r] + (b - g_tileoff[r]) * 256;
    int rend = g_off[r + 1];
    int nsub = min(4, (rend - base + 63) >> 6);

    // stage W1[r] via cp.async (group 0, with sub-tile 0)
    {
        int row = tid >> 2, seg = tid & 3;
        size_t src = ((size_t)r * DIN + row) * HID + seg * 32;
        uint32_t dh = smem_u32(Wh + row * PW1 + seg * 32);
        uint32_t dl = smem_u32(Wl + row * PW1 + seg * 32);
        #pragma unroll
        for (int q = 0; q < 4; ++q) {
            cpasync16(dh + q * 16, g_w1h + src + q * 8);
            cpasync16(dl + q * 16, g_w1l + src + q * 8);
        }
    }

    int e = tid >> 2, p = tid & 3;
    // prefetch lambda (macro-style): sub-tile ss into buffer bb
    auto prefetch = [&](int ss, int bb) {
        int gi = base + ss * 64 + e;
        int row = 0;
        bool v = gi < rend;
        if (v) row = g_esrc1[gi];
        if (p == 0) sdst[bb][e] = v ? g_edst[gi] : 0;
        const __nv_bfloat16* sh = g_embh + (size_t)row * DIN + p * 16;
        const __nv_bfloat16* sl = g_embl + (size_t)row * DIN + p * 16;
        uint32_t dh = smem_u32(sm + SM1_A + bb * SM1_ABUF + e * PA1 + p * 16);
        uint32_t dl = dh + (64 * PA1) * 2;
        cpasync16(dh, sh); cpasync16(dh + 16, sh + 8);
        cpasync16(dl, sl); cpasync16(dl + 16, sl + 8);
        cp_commit();
    };
    prefetch(0, 0);

    int wid = tid >> 5, lane = tid & 31;
    int wm = wid & 1, wn = wid >> 1;
    int mbase = 32 * wm, nbase = 32 * wn;
    uint32_t aBase = smem_u32(sm + SM1_A) +
        (((mbase + (lane & 15)) * PA1 + 8 * (lane >> 4)) << 1);
    uint32_t bOffH = smem_u32(Wh) +
        (((((lane & 7) + 8 * ((lane >> 3) & 1)) * PW1) + nbase + 8 * (lane >> 4)) << 1);
    uint32_t bOffL = bOffH + (SM1_WL << 1);

    for (int s = 0; s < nsub; ++s) {
        cp_wait0();
        __syncthreads();
        if (s + 1 < nsub) prefetch(s + 1, (s + 1) & 1);

        uint32_t aOffH = aBase + (s & 1) * (SM1_ABUF << 1);
        uint32_t aOffL = aOffH + ((64 * PA1) << 1);

        float c[2][4][4];
        #pragma unroll
        for (int mt = 0; mt < 2; ++mt)
            #pragma unroll
            for (int j = 0; j < 4; ++j)
                #pragma unroll
                for (int q = 0; q < 4; ++q) c[mt][j][q] = 0.f;

        #pragma unroll
        for (int ks = 0; ks < 4; ++ks) {
            int kk = ks * 16;
            uint32_t ah[2][4], al[2][4], bh[2][4], bl[2][4];
            #pragma unroll
            for (int mt = 0; mt < 2; ++mt) {
                ldsm_x4(ah[mt], aOffH + ((16 * mt * PA1 + kk) << 1));
                ldsm_x4(al[mt], aOffL + ((16 * mt * PA1 + kk) << 1));
            }
            #pragma unroll
            for (int pp = 0; pp < 2; ++pp) {
                ldsm_x4t(bh[pp], bOffH + ((kk * PW1) << 1) + pp * 32);
                ldsm_x4t(bl[pp], bOffL + ((kk * PW1) << 1) + pp * 32);
            }
            #pragma unroll
            for (int mt = 0; mt < 2; ++mt)
                #pragma unroll
                for (int j = 0; j < 4; ++j) {
                    int pp = j >> 1, w = j & 1;
                    mma_bf16(c[mt][j], ah[mt], bh[pp][2 * w], bh[pp][2 * w + 1]);
                    mma_bf16(c[mt][j], ah[mt], bl[pp][2 * w], bl[pp][2 * w + 1]);
                    mma_bf16(c[mt][j], al[mt], bh[pp][2 * w], bh[pp][2 * w + 1]);
                }
        }

        // scatter straight from fragments: red.v2, 32B sector per 4-lane group
        int M = min(64, rend - (base + s * 64));
        #pragma unroll
        for (int mt = 0; mt < 2; ++mt) {
            int r0 = mbase + 16 * mt + (lane >> 2);
            #pragma unroll
            for (int rr = 0; rr < 2; ++rr) {
                int row = r0 + 8 * rr;
                if (row < M) {
                    float* bp = g_x1acc + (size_t)sdst[s & 1][row] * HID;
                    #pragma unroll
                    for (int j = 0; j < 4; ++j) {
                        int col = nbase + 8 * j + 2 * (lane & 3);
                        red2(bp + col, c[mt][j][2 * rr], c[mt][j][2 * rr + 1]);
                    }
                }
            }
        }
    }
}

// ---------------- LN1 + ReLU -> bf16 hi/lo -----------------------------------
__global__ void k_ln1(const float* __restrict__ g, const float* __restrict__ bb, int N) {
    int w = (blockIdx.x * blockDim.x + threadIdx.x) >> 5;
    int lane = threadIdx.x & 31;
    if (w >= N) return;
    float4 v = ((const float4*)(g_x1acc + (size_t)w * HID))[lane];
    float s = v.x + v.y + v.z + v.w;
    #pragma unroll
    for (int o = 16; o; o >>= 1) s += __shfl_xor_sync(0xffffffffu, s, o);
    float mu = s * (1.f / HID);
    float dx = v.x - mu, dy = v.y - mu, dz = v.z - mu, dw = v.w - mu;
    float q = dx * dx + dy * dy + dz * dz + dw * dw;
    #pragma unroll
    for (int o = 16; o; o >>= 1) q += __shfl_xor_sync(0xffffffffu, q, o);
    float inv = rsqrtf(q * (1.f / HID) + 1e-5f);
    float4 gv = ((const float4*)g)[lane];
    float4 bv = ((const float4*)bb)[lane];
    float o0 = fmaxf(dx * inv * gv.x + bv.x, 0.f);
    float o1 = fmaxf(dy * inv * gv.y + bv.y, 0.f);
    float o2 = fmaxf(dz * inv * gv.z + bv.z, 0.f);
    float o3 = fmaxf(dw * inv * gv.w + bv.w, 0.f);
    __nv_bfloat16 h[4], l[4];
    split_bf16(o0, h[0], l[0]); split_bf16(o1, h[1], l[1]);
    split_bf16(o2, h[2], l[2]); split_bf16(o3, h[3], l[3]);
    ((uint2*)(g_x1h + (size_t)w * HID))[lane] = *(uint2*)h;
    ((uint2*)(g_x1l + (size_t)w * HID))[lane] = *(uint2*)l;
}

// ---------------- layer-2: 256 edges/block, pipelined 64x64x128 sub-tiles ----
#define PA2 136
#define PW2 72
#define SM2_WL   (128 * PW2)
#define SM2_A    (2 * 128 * PW2)
#define SM2_ABUF (2 * 64 * PA2)
#define SMEM2_BYTES ((SM2_A + 2 * SM2_ABUF) * 2)

__global__ void __launch_bounds__(256) k_gemm2() {
    extern __shared__ __nv_bfloat16 sm[];
    __nv_bfloat16* Wh = sm;
    __nv_bfloat16* Wl = sm + SM2_WL;
    __shared__ int sdst[2][64];

    int b = blockIdx.x;
    if (b >= g_tileoff[RNUM]) return;
    int tid = threadIdx.x;
    int r = 0;
    while (g_tileoff[r + 1] <= b) ++r;
    int base = g_off[r] + (b - g_tileoff[r]) * 256;
    int rend = g_off[r + 1];
    int nsub = min(4, (rend - base + 63) >> 6);

    // stage W2[r]: row=t>>1 (128 rows), half=t&1 (32 elems)
    {
        int row = tid >> 1, half = tid & 1;
        size_t src = ((size_t)r * HID + row) * DIN + half * 32;
        uint32_t dh = smem_u32(Wh + row * PW2 + half * 32);
        uint32_t dl = smem_u32(Wl + row * PW2 + half * 32);
        #pragma unroll
        for (int q = 0; q < 4; ++q) {
            cpasync16(dh + q * 16, g_w2h + src + q * 8);
            cpasync16(dl + q * 16, g_w2l + src + q * 8);
        }
    }

    int e = tid >> 2, p = tid & 3;
    auto prefetch = [&](int ss, int bb) {
        int gi = base + ss * 64 + e;
        int row = 0;
        bool v = gi < rend;
        if (v) row = g_esrc2[gi];
        if (p == 0) sdst[bb][e] = v ? g_edst[gi] : 0;
        const __nv_bfloat16* sh = g_x1h + (size_t)row * HID + p * 32;
        const __nv_bfloat16* sl = g_x1l + (size_t)row * HID + p * 32;
        uint32_t dh = smem_u32(sm + SM2_A + bb * SM2_ABUF + e * PA2 + p * 32);
        uint32_t dl = dh + (64 * PA2) * 2;
        #pragma unroll
        for (int q = 0; q < 4; ++q) {
            cpasync16(dh + q * 16, sh + q * 8);
            cpasync16(dl + q * 16, sl + q * 8);
        }
        cp_commit();
    };
    prefetch(0, 0);

    int wid = tid >> 5, lane = tid & 31;
    int wm = wid & 1, wn = wid >> 1;
    int mbase = 32 * wm, nbase = 16 * wn;
    uint32_t aBase = smem_u32(sm + SM2_A) +
        (((mbase + (lane & 15)) * PA2 + 8 * (lane >> 4)) << 1);
    uint32_t bOffH = smem_u32(Wh) +
        (((((lane & 7) + 8 * ((lane >> 3) & 1)) * PW2) + nbase + 8 * (lane >> 4)) << 1);
    uint32_t bOffL = bOffH + (SM2_WL << 1);

    for (int s = 0; s < nsub; ++s) {
        cp_wait0();
        __syncthreads();
        if (s + 1 < nsub) prefetch(s + 1, (s + 1) & 1);

        uint32_t aOffH = aBase + (s & 1) * (SM2_ABUF << 1);
        uint32_t aOffL = aOffH + ((64 * PA2) << 1);

        float c[2][2][4];
        #pragma unroll
        for (int mt = 0; mt < 2; ++mt)
            #pragma unroll
            for (int j = 0; j < 2; ++j)
                #pragma unroll
                for (int q = 0; q < 4; ++q) c[mt][j][q] = 0.f;

        #pragma unroll
        for (int ks = 0; ks < 8; ++ks) {
            int kk = ks * 16;
            uint32_t ah[2][4], al[2][4], bh[4], bl[4];
            #pragma unroll
            for (int mt = 0; mt < 2; ++mt) {
                ldsm_x4(ah[mt], aOffH + ((16 * mt * PA2 + kk) << 1));
                ldsm_x4(al[mt], aOffL + ((16 * mt * PA2 + kk) << 1));
            }
            ldsm_x4t(bh, bOffH + ((kk * PW2) << 1));
            ldsm_x4t(bl, bOffL + ((kk * PW2) << 1));
            #pragma unroll
            for (int mt = 0; mt < 2; ++mt)
                #pragma unroll
                for (int j = 0; j < 2; ++j) {
                    mma_bf16(c[mt][j], ah[mt], bh[2 * j], bh[2 * j + 1]);
                    mma_bf16(c[mt][j], ah[mt], bl[2 * j], bl[2 * j + 1]);
                    mma_bf16(c[mt][j], al[mt], bh[2 * j], bh[2 * j + 1]);
                }
        }

        int M = min(64, rend - (base + s * 64));
        #pragma unroll
        for (int mt = 0; mt < 2; ++mt) {
            int r0 = mbase + 16 * mt + (lane >> 2);
            #pragma unroll
            for (int rr = 0; rr < 2; ++rr) {
                int row = r0 + 8 * rr;
                if (row < M) {
                    float* bp = g_x2acc + (size_t)sdst[s & 1][row] * DIN;
                    #pragma unroll
                    for (int j = 0; j < 2; ++j) {
                        int col = nbase + 8 * j + 2 * (lane & 3);
                        red2(bp + col, c[mt][j][2 * rr], c[mt][j][2 * rr + 1]);
                    }
                }
            }
        }
    }
}

// ---------------- LN2 + residual ---------------------------------------------
__global__ void k_ln2res(const int* __restrict__ nid, const float* __restrict__ emb,
                         const float* __restrict__ g, const float* __restrict__ bb,
                         float* __restrict__ out, int N) {
    int w = (blockIdx.x * blockDim.x + threadIdx.x) >> 5;
    int lane = threadIdx.x & 31;
    if (w >= N) return;
    float2 v = ((const float2*)(g_x2acc + (size_t)w * DIN))[lane];
    float s = v.x + v.y;
    #pragma unroll
    for (int o = 16; o; o >>= 1) s += __shfl_xor_sync(0xffffffffu, s, o);
    float mu = s * (1.f / DIN);
    float dx = v.x - mu, dy = v.y - mu;
    float q = dx * dx + dy * dy;
    #pragma unroll
    for (int o = 16; o; o >>= 1) q += __shfl_xor_sync(0xffffffffu, q, o);
    float inv = rsqrtf(q * (1.f / DIN) + 1e-5f);
    float2 gv = ((const float2*)g)[lane];
    float2 bv = ((const float2*)bb)[lane];
    float2 xr = ((const float2*)(emb + (size_t)nid[w] * DIN))[lane];
    float2 o2;
    o2.x = dx * inv * gv.x + bv.x + xr.x;
    o2.y = dy * inv * gv.y + bv.y + xr.y;
    ((float2*)(out + (size_t)w * DIN))[lane] = o2;
}

// ---------------- launch -----------------------------------------------------
extern "C" void kernel_launch(void* const* d_in, const int* in_sizes, int n_in,
                              void* d_out, int out_size) {
    const int*   nid   = (const int*)d_in[0];
    const int*   eidx  = (const int*)d_in[1];
    const int*   etype = (const int*)d_in[2];
    const float* emb   = (const float*)d_in[3];
    const float* W1    = (const float*)d_in[4];
    const float* W2    = (const float*)d_in[5];
    const float* ln1g  = (const float*)d_in[6];
    const float* ln1b  = (const float*)d_in[7];
    const float* ln2g  = (const float*)d_in[8];
    const float* ln2b  = (const float*)d_in[9];
    float* out = (float*)d_out;

    int N = in_sizes[0];
    int E = in_sizes[2];

    cudaFuncSetAttribute(k_gemm1, cudaFuncAttributeMaxDynamicSharedMemorySize, SMEM1_BYTES);
    cudaFuncSetAttribute(k_gemm2, cudaFuncAttributeMaxDynamicSharedMemorySize, SMEM2_BYTES);

    int blocks = (E + 255) / 256 + RNUM;

    k_prep<<<1024, 256>>>(emb, W1, W2, N);
    k_hist<<<512, 256>>>(etype, E);
    k_scan<<<1, 32>>>();
    k_bucket<<<(E + 255) / 256, 256>>>(etype, eidx, nid, E);
    k_gemm1<<<blocks, 256, SMEM1_BYTES>>>();
    k_ln1<<<(N * 32 + 255) / 256, 256>>>(ln1g, ln1b, N);
    k_gemm2<<<blocks, 256, SMEM2_BYTES>>>();
    k_ln2res<<<(N * 32 + 255) / 256, 256>>>(nid, emb, ln2g, ln2b, out, N);
}

// round 5
// speedup vs baseline: 3.0113x; 1.0180x over previous
#include <cuda_runtime.h>
#include <cuda_bf16.h>
#include <cstdint>

#define MAXN 50000
#define MAXE 600000
#define RNUM 16
#define DIN  64
#define HID  128

// ---------------- scratch ----------------------------------------------------
__device__ float g_x1acc[(size_t)MAXN * HID];
__device__ float g_x2acc[(size_t)MAXN * DIN];
__device__ __nv_bfloat16 g_embh[(size_t)MAXN * DIN];
__device__ __nv_bfloat16 g_embl[(size_t)MAXN * DIN];
__device__ __nv_bfloat16 g_x1h[(size_t)MAXN * HID];
__device__ __nv_bfloat16 g_x1l[(size_t)MAXN * HID];
__device__ __nv_bfloat16 g_w1h[RNUM * DIN * HID];
__device__ __nv_bfloat16 g_w1l[RNUM * DIN * HID];
__device__ __nv_bfloat16 g_w2h[RNUM * HID * DIN];
__device__ __nv_bfloat16 g_w2l[RNUM * HID * DIN];
__device__ int g_esrc1[MAXE];
__device__ int g_esrc2[MAXE];
__device__ int g_edst[MAXE];
__device__ int g_cnt[RNUM];
__device__ int g_off[RNUM + 1];
__device__ int g_cursor[RNUM];
__device__ int g_tileoff[RNUM + 1];

// ---------------- PTX helpers ------------------------------------------------
__device__ __forceinline__ uint32_t smem_u32(const void* p) {
    return (uint32_t)__cvta_generic_to_shared(p);
}
__device__ __forceinline__ void ldsm_x4(uint32_t* r, uint32_t a) {
    asm volatile("ldmatrix.sync.aligned.m8n8.x4.shared.b16 {%0,%1,%2,%3}, [%4];\n"
                 : "=r"(r[0]), "=r"(r[1]), "=r"(r[2]), "=r"(r[3]) : "r"(a));
}
__device__ __forceinline__ void ldsm_x4t(uint32_t* r, uint32_t a) {
    asm volatile("ldmatrix.sync.aligned.m8n8.x4.trans.shared.b16 {%0,%1,%2,%3}, [%4];\n"
                 : "=r"(r[0]), "=r"(r[1]), "=r"(r[2]), "=r"(r[3]) : "r"(a));
}
__device__ __forceinline__ void mma_bf16(float* c, const uint32_t* a, uint32_t b0, uint32_t b1) {
    asm volatile("mma.sync.aligned.m16n8k16.row.col.f32.bf16.bf16.f32 "
                 "{%0,%1,%2,%3},{%4,%5,%6,%7},{%8,%9},{%0,%1,%2,%3};\n"
                 : "+f"(c[0]), "+f"(c[1]), "+f"(c[2]), "+f"(c[3])
                 : "r"(a[0]), "r"(a[1]), "r"(a[2]), "r"(a[3]), "r"(b0), "r"(b1));
}
__device__ __forceinline__ void cpasync16(uint32_t saddr, const void* g) {
    asm volatile("cp.async.cg.shared.global [%0], [%1], 16;\n" :: "r"(saddr), "l"(g));
}
__device__ __forceinline__ void cp_commit() {
    asm volatile("cp.async.commit_group;\n");
}
__device__ __forceinline__ void cp_wait0() {
    asm volatile("cp.async.wait_group 0;\n");
}
__device__ __forceinline__ void red4(float* p, float x, float y, float z, float w) {
    asm volatile("red.global.add.v4.f32 [%0], {%1,%2,%3,%4};\n"
                 :: "l"(p), "f"(x), "f"(y), "f"(z), "f"(w) : "memory");
}
__device__ __forceinline__ void split_bf16(float v, __nv_bfloat16& h, __nv_bfloat16& l) {
    h = __float2bfloat16(v);
    l = __float2bfloat16(v - __bfloat162float(h));
}

// ---------------- prep: zero + convert weights/emb ---------------------------
__global__ void k_prep(const float* __restrict__ emb, const float* __restrict__ W1,
                       const float* __restrict__ W2, int N) {
    int stride = gridDim.x * blockDim.x;
    int i = blockIdx.x * blockDim.x + threadIdx.x;
    float4 z = make_float4(0.f, 0.f, 0.f, 0.f);
    int n1 = N * (HID / 4);
    for (int k = i; k < n1; k += stride) ((float4*)g_x1acc)[k] = z;
    int n2 = N * (DIN / 4);
    for (int k = i; k < n2; k += stride) ((float4*)g_x2acc)[k] = z;
    int ne = N * DIN;
    for (int k = i; k < ne; k += stride) split_bf16(emb[k], g_embh[k], g_embl[k]);
    for (int k = i; k < RNUM * DIN * HID; k += stride) split_bf16(W1[k], g_w1h[k], g_w1l[k]);
    for (int k = i; k < RNUM * HID * DIN; k += stride) split_bf16(W2[k], g_w2h[k], g_w2l[k]);
    if (blockIdx.x == 0 && threadIdx.x < RNUM) g_cnt[threadIdx.x] = 0;
}

// ---------------- histogram / scan / bucket ----------------------------------
__global__ void k_hist(const int* __restrict__ et, int E) {
    __shared__ int s[RNUM];
    if (threadIdx.x < RNUM) s[threadIdx.x] = 0;
    __syncthreads();
    int stride = gridDim.x * blockDim.x;
    for (int i = blockIdx.x * blockDim.x + threadIdx.x; i < E; i += stride)
        atomicAdd(&s[et[i]], 1);
    __syncthreads();
    if (threadIdx.x < RNUM && s[threadIdx.x]) atomicAdd(&g_cnt[threadIdx.x], s[threadIdx.x]);
}
__global__ void k_scan() {
    if (threadIdx.x == 0 && blockIdx.x == 0) {
        int o = 0, t = 0;
        for (int r = 0; r < RNUM; ++r) {
            g_off[r] = o; g_cursor[r] = o; g_tileoff[r] = t;
            o += g_cnt[r];
            t += (g_cnt[r] + 255) >> 8;
        }
        g_off[RNUM] = o; g_tileoff[RNUM] = t;
    }
}
__global__ void k_bucket(const int* __restrict__ et, const int* __restrict__ eidx,
                         const int* __restrict__ nid, int E) {
    __shared__ int lcnt[RNUM], lbase[RNUM];
    int e = blockIdx.x * 256 + threadIdx.x;
    if (threadIdx.x < RNUM) lcnt[threadIdx.x] = 0;
    __syncthreads();
    int r = 0, rank = 0, s = 0, d = 0;
    if (e < E) {
        r = et[e]; s = eidx[e]; d = eidx[E + e];
        rank = atomicAdd(&lcnt[r], 1);
    }
    __syncthreads();
    if (threadIdx.x < RNUM && lcnt[threadIdx.x])
        lbase[threadIdx.x] = atomicAdd(&g_cursor[threadIdx.x], lcnt[threadIdx.x]);
    __syncthreads();
    if (e < E) {
        int pos = lbase[r] + rank;
        g_esrc1[pos] = nid[s];
        g_esrc2[pos] = s;
        g_edst[pos]  = d;
    }
}

// ---------------- layer-1: 256 edges/block, pipelined 64x128x64 sub-tiles ----
#define PA1 72
#define PW1 136
#define SM1_WL   (64 * PW1)
#define SM1_A    (2 * 64 * PW1)
#define SM1_ABUF (2 * 64 * PA1)
#define SMEM1_BYTES ((SM1_A + 2 * SM1_ABUF) * 2)

__global__ void __launch_bounds__(256) k_gemm1() {
    extern __shared__ __nv_bfloat16 sm[];
    __nv_bfloat16* Wh = sm;
    __nv_bfloat16* Wl = sm + SM1_WL;
    __shared__ int sdst[2][64];

    int b = blockIdx.x;
    if (b >= g_tileoff[RNUM]) return;
    int tid = threadIdx.x;
    int r = 0;
    while (g_tileoff[r + 1] <= b) ++r;
    int base = g_off[r] + (b - g_tileoff[r]) * 256;
    int rend = g_off[r + 1];
    int nsub = min(4, (rend - base + 63) >> 6);

    // stage W1[r] (group committed with sub-tile 0)
    {
        int row = tid >> 2, seg = tid & 3;
        size_t src = ((size_t)r * DIN + row) * HID + seg * 32;
        uint32_t dh = smem_u32(Wh + row * PW1 + seg * 32);
        uint32_t dl = smem_u32(Wl + row * PW1 + seg * 32);
        #pragma unroll
        for (int q = 0; q < 4; ++q) {
            cpasync16(dh + q * 16, g_w1h + src + q * 8);
            cpasync16(dl + q * 16, g_w1l + src + q * 8);
        }
    }

    int e = tid >> 2, p = tid & 3;
    auto prefetch = [&](int ss, int bb) {
        int gi = base + ss * 64 + e;
        int row = 0;
        bool v = gi < rend;
        if (v) row = g_esrc1[gi];
        if (p == 0) sdst[bb][e] = v ? g_edst[gi] : 0;
        const __nv_bfloat16* sh = g_embh + (size_t)row * DIN + p * 16;
        const __nv_bfloat16* sl = g_embl + (size_t)row * DIN + p * 16;
        uint32_t dh = smem_u32(sm + SM1_A + bb * SM1_ABUF + e * PA1 + p * 16);
        uint32_t dl = dh + (64 * PA1) * 2;
        cpasync16(dh, sh); cpasync16(dh + 16, sh + 8);
        cpasync16(dl, sl); cpasync16(dl + 16, sl + 8);
        cp_commit();
    };
    prefetch(0, 0);

    int wid = tid >> 5, lane = tid & 31;
    int wm = wid & 1, wn = wid >> 1;
    int mbase = 32 * wm, nbase = 32 * wn;
    uint32_t aBase = smem_u32(sm + SM1_A) +
        (((mbase + (lane & 15)) * PA1 + 8 * (lane >> 4)) << 1);
    uint32_t bOffH = smem_u32(Wh) +
        (((((lane & 7) + 8 * ((lane >> 3) & 1)) * PW1) + nbase + 8 * (lane >> 4)) << 1);
    uint32_t bOffL = bOffH + (SM1_WL << 1);

    int t = lane & 3;
    bool evenp = (t & 1) == 0;

    for (int s = 0; s < nsub; ++s) {
        cp_wait0();
        __syncthreads();
        if (s + 1 < nsub) prefetch(s + 1, (s + 1) & 1);

        uint32_t aOffH = aBase + (s & 1) * (SM1_ABUF << 1);
        uint32_t aOffL = aOffH + ((64 * PA1) << 1);

        float c[2][4][4];
        #pragma unroll
        for (int mt = 0; mt < 2; ++mt)
            #pragma unroll
            for (int j = 0; j < 4; ++j)
                #pragma unroll
                for (int q = 0; q < 4; ++q) c[mt][j][q] = 0.f;

        #pragma unroll
        for (int ks = 0; ks < 4; ++ks) {
            int kk = ks * 16;
            uint32_t ah[2][4], al[2][4], bh[2][4], bl[2][4];
            #pragma unroll
            for (int mt = 0; mt < 2; ++mt) {
                ldsm_x4(ah[mt], aOffH + ((16 * mt * PA1 + kk) << 1));
                ldsm_x4(al[mt], aOffL + ((16 * mt * PA1 + kk) << 1));
            }
            #pragma unroll
            for (int pp = 0; pp < 2; ++pp) {
                ldsm_x4t(bh[pp], bOffH + ((kk * PW1) << 1) + pp * 32);
                ldsm_x4t(bl[pp], bOffL + ((kk * PW1) << 1) + pp * 32);
            }
            #pragma unroll
            for (int mt = 0; mt < 2; ++mt)
                #pragma unroll
                for (int j = 0; j < 4; ++j) {
                    int pp = j >> 1, w = j & 1;
                    mma_bf16(c[mt][j], ah[mt], bh[pp][2 * w], bh[pp][2 * w + 1]);
                    mma_bf16(c[mt][j], ah[mt], bl[pp][2 * w], bl[pp][2 * w + 1]);
                    mma_bf16(c[mt][j], al[mt], bh[pp][2 * w], bh[pp][2 * w + 1]);
                }
        }

        // shuffle-combined red.v4 scatter: even lanes -> row A, odd lanes -> row B
        int M = min(64, rend - (base + s * 64));
        #pragma unroll
        for (int mt = 0; mt < 2; ++mt) {
            int rowA = mbase + 16 * mt + (lane >> 2);
            int myrow = evenp ? rowA : rowA + 8;
            bool ok = myrow < M;
            float* bp = g_x1acc + (size_t)sdst[s & 1][ok ? myrow : 0] * HID;
            #pragma unroll
            for (int j = 0; j < 4; ++j) {
                float sx = evenp ? c[mt][j][2] : c[mt][j][0];
                float sy = evenp ? c[mt][j][3] : c[mt][j][1];
                float rx = __shfl_xor_sync(0xffffffffu, sx, 1);
                float ry = __shfl_xor_sync(0xffffffffu, sy, 1);
                if (ok) {
                    if (evenp)
                        red4(bp + nbase + 8 * j + 2 * t,
                             c[mt][j][0], c[mt][j][1], rx, ry);
                    else
                        red4(bp + nbase + 8 * j + 2 * (t - 1),
                             rx, ry, c[mt][j][2], c[mt][j][3]);
                }
            }
        }
    }
}

// ---------------- LN1 + ReLU -> bf16 hi/lo -----------------------------------
__global__ void k_ln1(const float* __restrict__ g, const float* __restrict__ bb, int N) {
    int w = (blockIdx.x * blockDim.x + threadIdx.x) >> 5;
    int lane = threadIdx.x & 31;
    if (w >= N) return;
    float4 v = ((const float4*)(g_x1acc + (size_t)w * HID))[lane];
    float s = v.x + v.y + v.z + v.w;
    #pragma unroll
    for (int o = 16; o; o >>= 1) s += __shfl_xor_sync(0xffffffffu, s, o);
    float mu = s * (1.f / HID);
    float dx = v.x - mu, dy = v.y - mu, dz = v.z - mu, dw = v.w - mu;
    float q = dx * dx + dy * dy + dz * dz + dw * dw;
    #pragma unroll
    for (int o = 16; o; o >>= 1) q += __shfl_xor_sync(0xffffffffu, q, o);
    float inv = rsqrtf(q * (1.f / HID) + 1e-5f);
    float4 gv = ((const float4*)g)[lane];
    float4 bv = ((const float4*)bb)[lane];
    float o0 = fmaxf(dx * inv * gv.x + bv.x, 0.f);
    float o1 = fmaxf(dy * inv * gv.y + bv.y, 0.f);
    float o2 = fmaxf(dz * inv * gv.z + bv.z, 0.f);
    float o3 = fmaxf(dw * inv * gv.w + bv.w, 0.f);
    __nv_bfloat16 h[4], l[4];
    split_bf16(o0, h[0], l[0]); split_bf16(o1, h[1], l[1]);
    split_bf16(o2, h[2], l[2]); split_bf16(o3, h[3], l[3]);
    ((uint2*)(g_x1h + (size_t)w * HID))[lane] = *(uint2*)h;
    ((uint2*)(g_x1l + (size_t)w * HID))[lane] = *(uint2*)l;
}

// ---------------- layer-2: 256 edges/block, pipelined 64x64x128 sub-tiles ----
#define PA2 136
#define PW2 72
#define SM2_WL   (128 * PW2)
#define SM2_A    (2 * 128 * PW2)
#define SM2_ABUF (2 * 64 * PA2)
#define SMEM2_BYTES ((SM2_A + 2 * SM2_ABUF) * 2)

__global__ void __launch_bounds__(256) k_gemm2() {
    extern __shared__ __nv_bfloat16 sm[];
    __nv_bfloat16* Wh = sm;
    __nv_bfloat16* Wl = sm + SM2_WL;
    __shared__ int sdst[2][64];

    int b = blockIdx.x;
    if (b >= g_tileoff[RNUM]) return;
    int tid = threadIdx.x;
    int r = 0;
    while (g_tileoff[r + 1] <= b) ++r;
    int base = g_off[r] + (b - g_tileoff[r]) * 256;
    int rend = g_off[r + 1];
    int nsub = min(4, (rend - base + 63) >> 6);

    {
        int row = tid >> 1, half = tid & 1;
        size_t src = ((size_t)r * HID + row) * DIN + half * 32;
        uint32_t dh = smem_u32(Wh + row * PW2 + half * 32);
        uint32_t dl = smem_u32(Wl + row * PW2 + half * 32);
        #pragma unroll
        for (int q = 0; q < 4; ++q) {
            cpasync16(dh + q * 16, g_w2h + src + q * 8);
            cpasync16(dl + q * 16, g_w2l + src + q * 8);
        }
    }

    int e = tid >> 2, p = tid & 3;
    auto prefetch = [&](int ss, int bb) {
        int gi = base + ss * 64 + e;
        int row = 0;
        bool v = gi < rend;
        if (v) row = g_esrc2[gi];
        if (p == 0) sdst[bb][e] = v ? g_edst[gi] : 0;
        const __nv_bfloat16* sh = g_x1h + (size_t)row * HID + p * 32;
        const __nv_bfloat16* sl = g_x1l + (size_t)row * HID + p * 32;
        uint32_t dh = smem_u32(sm + SM2_A + bb * SM2_ABUF + e * PA2 + p * 32);
        uint32_t dl = dh + (64 * PA2) * 2;
        #pragma unroll
        for (int q = 0; q < 4; ++q) {
            cpasync16(dh + q * 16, sh + q * 8);
            cpasync16(dl + q * 16, sl + q * 8);
        }
        cp_commit();
    };
    prefetch(0, 0);

    int wid = tid >> 5, lane = tid & 31;
    int wm = wid & 1, wn = wid >> 1;
    int mbase = 32 * wm, nbase = 16 * wn;
    uint32_t aBase = smem_u32(sm + SM2_A) +
        (((mbase + (lane & 15)) * PA2 + 8 * (lane >> 4)) << 1);
    uint32_t bOffH = smem_u32(Wh) +
        (((((lane & 7) + 8 * ((lane >> 3) & 1)) * PW2) + nbase + 8 * (lane >> 4)) << 1);
    uint32_t bOffL = bOffH + (SM2_WL << 1);

    // first wait: W + sub-tile 0 ready, then hoist W fragments to registers
    cp_wait0();
    __syncthreads();
    uint32_t wbh[8][4], wbl[8][4];
    #pragma unroll
    for (int ks = 0; ks < 8; ++ks) {
        ldsm_x4t(wbh[ks], bOffH + ((ks * 16 * PW2) << 1));
        ldsm_x4t(wbl[ks], bOffL + ((ks * 16 * PW2) << 1));
    }

    int t = lane & 3;
    bool evenp = (t & 1) == 0;

    for (int s = 0; s < nsub; ++s) {
        if (s > 0) { cp_wait0(); __syncthreads(); }
        if (s + 1 < nsub) prefetch(s + 1, (s + 1) & 1);

        uint32_t aOffH = aBase + (s & 1) * (SM2_ABUF << 1);
        uint32_t aOffL = aOffH + ((64 * PA2) << 1);

        float c[2][2][4];
        #pragma unroll
        for (int mt = 0; mt < 2; ++mt)
            #pragma unroll
            for (int j = 0; j < 2; ++j)
                #pragma unroll
                for (int q = 0; q < 4; ++q) c[mt][j][q] = 0.f;

        #pragma unroll
        for (int ks = 0; ks < 8; ++ks) {
            int kk = ks * 16;
            uint32_t ah[2][4], al[2][4];
            #pragma unroll
            for (int mt = 0; mt < 2; ++mt) {
                ldsm_x4(ah[mt], aOffH + ((16 * mt * PA2 + kk) << 1));
                ldsm_x4(al[mt], aOffL + ((16 * mt * PA2 + kk) << 1));
            }
            #pragma unroll
            for (int mt = 0; mt < 2; ++mt)
                #pragma unroll
                for (int j = 0; j < 2; ++j) {
                    mma_bf16(c[mt][j], ah[mt], wbh[ks][2 * j], wbh[ks][2 * j + 1]);
                    mma_bf16(c[mt][j], ah[mt], wbl[ks][2 * j], wbl[ks][2 * j + 1]);
                    mma_bf16(c[mt][j], al[mt], wbh[ks][2 * j], wbh[ks][2 * j + 1]);
                }
        }

        int M = min(64, rend - (base + s * 64));
        #pragma unroll
        for (int mt = 0; mt < 2; ++mt) {
            int rowA = mbase + 16 * mt + (lane >> 2);
            int myrow = evenp ? rowA : rowA + 8;
            bool ok = myrow < M;
            float* bp = g_x2acc + (size_t)sdst[s & 1][ok ? myrow : 0] * DIN;
            #pragma unroll
            for (int j = 0; j < 2; ++j) {
                float sx = evenp ? c[mt][j][2] : c[mt][j][0];
                float sy = evenp ? c[mt][j][3] : c[mt][j][1];
                float rx = __shfl_xor_sync(0xffffffffu, sx, 1);
                float ry = __shfl_xor_sync(0xffffffffu, sy, 1);
                if (ok) {
                    if (evenp)
                        red4(bp + nbase + 8 * j + 2 * t,
                             c[mt][j][0], c[mt][j][1], rx, ry);
                    else
                        red4(bp + nbase + 8 * j + 2 * (t - 1),
                             rx, ry, c[mt][j][2], c[mt][j][3]);
                }
            }
        }
    }
}

// ---------------- LN2 + residual ---------------------------------------------
__global__ void k_ln2res(const int* __restrict__ nid, const float* __restrict__ emb,
                         const float* __restrict__ g, const float* __restrict__ bb,
                         float* __restrict__ out, int N) {
    int w = (blockIdx.x * blockDim.x + threadIdx.x) >> 5;
    int lane = threadIdx.x & 31;
    if (w >= N) return;
    float2 v = ((const float2*)(g_x2acc + (size_t)w * DIN))[lane];
    float s = v.x + v.y;
    #pragma unroll
    for (int o = 16; o; o >>= 1) s += __shfl_xor_sync(0xffffffffu, s, o);
    float mu = s * (1.f / DIN);
    float dx = v.x - mu, dy = v.y - mu;
    float q = dx * dx + dy * dy;
    #pragma unroll
    for (int o = 16; o; o >>= 1) q += __shfl_xor_sync(0xffffffffu, q, o);
    float inv = rsqrtf(q * (1.f / DIN) + 1e-5f);
    float2 gv = ((const float2*)g)[lane];
    float2 bv = ((const float2*)bb)[lane];
    float2 xr = ((const float2*)(emb + (size_t)nid[w] * DIN))[lane];
    float2 o2;
    o2.x = dx * inv * gv.x + bv.x + xr.x;
    o2.y = dy * inv * gv.y + bv.y + xr.y;
    ((float2*)(out + (size_t)w * DIN))[lane] = o2;
}

// ---------------- launch -----------------------------------------------------
extern "C" void kernel_launch(void* const* d_in, const int* in_sizes, int n_in,
                              void* d_out, int out_size) {
    const int*   nid   = (const int*)d_in[0];
    const int*   eidx  = (const int*)d_in[1];
    const int*   etype = (const int*)d_in[2];
    const float* emb   = (const float*)d_in[3];
    const float* W1    = (const float*)d_in[4];
    const float* W2    = (const float*)d_in[5];
    const float* ln1g  = (const float*)d_in[6];
    const float* ln1b  = (const float*)d_in[7];
    const float* ln2g  = (const float*)d_in[8];
    const float* ln2b  = (const float*)d_in[9];
    float* out = (float*)d_out;

    int N = in_sizes[0];
    int E = in_sizes[2];

    cudaFuncSetAttribute(k_gemm1, cudaFuncAttributeMaxDynamicSharedMemorySize, SMEM1_BYTES);
    cudaFuncSetAttribute(k_gemm2, cudaFuncAttributeMaxDynamicSharedMemorySize, SMEM2_BYTES);

    int blocks = (E + 255) / 256 + RNUM;

    k_prep<<<1024, 256>>>(emb, W1, W2, N);
    k_hist<<<512, 256>>>(etype, E);
    k_scan<<<1, 32>>>();
    k_bucket<<<(E + 255) / 256, 256>>>(etype, eidx, nid, E);
    k_gemm1<<<blocks, 256, SMEM1_BYTES>>>();
    k_ln1<<<(N * 32 + 255) / 256, 256>>>(ln1g, ln1b, N);
    k_gemm2<<<blocks, 256, SMEM2_BYTES>>>();
    k_ln2res<<<(N * 32 + 255) / 256, 256>>>(nid, emb, ln2g, ln2b, out, N);
}